// round 3
// baseline (speedup 1.0000x reference)
#include <cuda_runtime.h>

#define BATCH 8
#define NTOK 1032
#define CDIM 768
#define NHEAD 12
#define HD 64
#define SCALE 0.125f

// Scratch (static device globals; allocation-free)
__device__ float d_add[NTOK * NTOK + 64];              // +64 pad for float4 overread on last row
__device__ float d_Kbuf[BATCH * NHEAD * NTOK * HD];    // [b][h][n][d]
__device__ float d_Vbuf[BATCH * NHEAD * NTOK * HD];
__device__ float d_Obuf[BATCH * NTOK * CDIM];          // [b][n][h*64+d]

// ---------------------------------------------------------------------------
// Kernel 1: gaussian additive bias table (same for all b,h)
// add[i,j] = exp(-0.02*((ri-rj)^2+(ci-cj)^2)) for i,j >= 8 else 0
// ---------------------------------------------------------------------------
__global__ void add_kernel() {
    int idx = blockIdx.x * 256 + threadIdx.x;
    if (idx >= NTOK * NTOK + 64) return;
    float v = 0.0f;
    if (idx < NTOK * NTOK) {
        int i = idx / NTOK, j = idx - (idx / NTOK) * NTOK;
        if (i >= 8 && j >= 8) {
            int p = i - 8, q = j - 8;
            int dr = (p >> 5) - (q >> 5);
            int dc = (p & 31) - (q & 31);
            v = __expf(-0.02f * (float)(dr * dr + dc * dc));
        }
    }
    d_add[idx] = v;
}

// ---------------------------------------------------------------------------
// Kernel 2: KV GEMM.  out[m, c] = x[m,:] . qkv_w[768+c, :] + qkv_b[768+c]
// m in [0,8256), c in [0,1536).  Scatters into head-major d_Kbuf/d_Vbuf.
// ---------------------------------------------------------------------------
__global__ void gemm_kv(const float* __restrict__ x,
                        const float* __restrict__ w,
                        const float* __restrict__ bias) {
    __shared__ float As[16][64];   // [k][m]
    __shared__ float Bs[16][64];   // [k][c]
    int tid = threadIdx.x;
    int ty = tid >> 4, tx = tid & 15;
    int m0 = blockIdx.y * 64;
    int c0 = blockIdx.x * 64;      // 0..1535

    float acc[4][4];
#pragma unroll
    for (int u = 0; u < 4; u++)
#pragma unroll
        for (int e = 0; e < 4; e++) acc[u][e] = 0.0f;

    int lr = tid >> 2;             // 0..63
    int lq = (tid & 3) * 4;        // 0,4,8,12
    const float* xrow = x + (size_t)(m0 + lr) * CDIM;
    const float* wrow = w + (size_t)(CDIM + c0 + lr) * CDIM;

    for (int kt = 0; kt < CDIM; kt += 16) {
        float4 av = *(const float4*)(xrow + kt + lq);
        float4 wv = *(const float4*)(wrow + kt + lq);
        As[lq + 0][lr] = av.x; As[lq + 1][lr] = av.y;
        As[lq + 2][lr] = av.z; As[lq + 3][lr] = av.w;
        Bs[lq + 0][lr] = wv.x; Bs[lq + 1][lr] = wv.y;
        Bs[lq + 2][lr] = wv.z; Bs[lq + 3][lr] = wv.w;
        __syncthreads();
#pragma unroll
        for (int k = 0; k < 16; k++) {
            float4 a4 = *(float4*)&As[k][ty * 4];
            float4 b4 = *(float4*)&Bs[k][tx * 4];
            float aa[4] = {a4.x, a4.y, a4.z, a4.w};
            float bb[4] = {b4.x, b4.y, b4.z, b4.w};
#pragma unroll
            for (int u = 0; u < 4; u++)
#pragma unroll
                for (int e = 0; e < 4; e++) acc[u][e] += aa[u] * bb[e];
        }
        __syncthreads();
    }

    float4 bv = *(const float4*)(bias + CDIM + c0 + tx * 4);
    bool isK = (c0 < CDIM);
    float* dst = isK ? d_Kbuf : d_Vbuf;
    int h = (isK ? c0 : (c0 - CDIM)) >> 6;
#pragma unroll
    for (int u = 0; u < 4; u++) {
        int m = m0 + ty * 4 + u;
        int bb = m / NTOK;
        int n = m - bb * NTOK;
        float4 o;
        o.x = acc[u][0] + bv.x; o.y = acc[u][1] + bv.y;
        o.z = acc[u][2] + bv.z; o.w = acc[u][3] + bv.w;
        *(float4*)&dst[(((size_t)bb * NHEAD + h) * NTOK + n) * HD + tx * 4] = o;
    }
}

// ---------------------------------------------------------------------------
// Kernel 3: flash attention.  Per (i-tile of 64 rows, b*h):
//   S = Ki . Kj^T * scale + add;  online softmax;  O += P . Vj
// ---------------------------------------------------------------------------
__global__ void attn_kernel() {
    extern __shared__ float sm[];
    float* KiT = sm;               // [64][64]  ([d][i])
    float* KjT = sm + 4096;        // [64][64]  ([d][j])
    float* Vj  = sm + 8192;        // [64][64]  ([j][d])
    float* PT  = sm + 12288;       // [64][68]  ([j][i], padded)

    int tid = threadIdx.x;
    int ty = tid >> 4, tx = tid & 15;
    int i0 = blockIdx.x * 64;
    int bh = blockIdx.y;
    const float* Kbh = d_Kbuf + (size_t)bh * NTOK * HD;
    const float* Vbh = d_Vbuf + (size_t)bh * NTOK * HD;

    int lr = tid >> 2;             // token row within tile: 0..63
    int lc = (tid & 3) * 4;        // base d offset; covers d = lc + s*16, s=0..3

    {   // load Ki (transposed [d][i]) — FULL 64x64 tile: 16 floats/thread
        int gi = i0 + lr;
        bool ok = (gi < NTOK);
        const float* base = Kbh + (size_t)gi * HD;
#pragma unroll
        for (int s = 0; s < 4; s++) {
            int d0 = lc + s * 16;
            float4 kv = ok ? *(const float4*)(base + d0) : make_float4(0, 0, 0, 0);
            KiT[(d0 + 0) * 64 + lr] = kv.x;
            KiT[(d0 + 1) * 64 + lr] = kv.y;
            KiT[(d0 + 2) * 64 + lr] = kv.z;
            KiT[(d0 + 3) * 64 + lr] = kv.w;
        }
    }

    float mrow[4], lsum[4], acc[4][4];
#pragma unroll
    for (int u = 0; u < 4; u++) {
        mrow[u] = -1e30f; lsum[u] = 0.0f;
#pragma unroll
        for (int e = 0; e < 4; e++) acc[u][e] = 0.0f;
    }

    const int NJT = (NTOK + 63) / 64;   // 17
    for (int jt = 0; jt < NJT; jt++) {
        int j0 = jt * 64;
        __syncthreads();
        {   // load Kj (transposed) + Vj (natural) — FULL 64x64 tiles
            int gj = j0 + lr;
            bool ok = (gj < NTOK);
            const float* kb = Kbh + (size_t)gj * HD;
            const float* vb = Vbh + (size_t)gj * HD;
#pragma unroll
            for (int s = 0; s < 4; s++) {
                int d0 = lc + s * 16;
                float4 kv = ok ? *(const float4*)(kb + d0) : make_float4(0, 0, 0, 0);
                float4 vv = ok ? *(const float4*)(vb + d0) : make_float4(0, 0, 0, 0);
                KjT[(d0 + 0) * 64 + lr] = kv.x;
                KjT[(d0 + 1) * 64 + lr] = kv.y;
                KjT[(d0 + 2) * 64 + lr] = kv.z;
                KjT[(d0 + 3) * 64 + lr] = kv.w;
                *(float4*)&Vj[lr * 64 + d0] = vv;
            }
        }
        __syncthreads();

        float S[4][4];
#pragma unroll
        for (int u = 0; u < 4; u++)
#pragma unroll
            for (int e = 0; e < 4; e++) S[u][e] = 0.0f;

#pragma unroll 8
        for (int k = 0; k < 64; k++) {
            float4 a4 = *(float4*)&KiT[k * 64 + ty * 4];
            float4 b4 = *(float4*)&KjT[k * 64 + tx * 4];
            float aa[4] = {a4.x, a4.y, a4.z, a4.w};
            float bb[4] = {b4.x, b4.y, b4.z, b4.w};
#pragma unroll
            for (int u = 0; u < 4; u++)
#pragma unroll
                for (int e = 0; e < 4; e++) S[u][e] += aa[u] * bb[e];
        }

        int irow = i0 + ty * 4;
        int jcol = j0 + tx * 4;
#pragma unroll
        for (int u = 0; u < 4; u++) {
            int gi = irow + u;
            int ai = (gi < NTOK) ? gi : (NTOK - 1);
            float4 a4 = *(const float4*)(d_add + (size_t)ai * NTOK + jcol);
            float ad[4] = {a4.x, a4.y, a4.z, a4.w};
#pragma unroll
            for (int e = 0; e < 4; e++) {
                float s = S[u][e] * SCALE + ad[e];
                S[u][e] = (jcol + e < NTOK) ? s : -1e30f;
            }
            float mt = fmaxf(fmaxf(S[u][0], S[u][1]), fmaxf(S[u][2], S[u][3]));
#pragma unroll
            for (int o = 8; o >= 1; o >>= 1)
                mt = fmaxf(mt, __shfl_xor_sync(0xffffffffu, mt, o, 16));
            float mnew = fmaxf(mrow[u], mt);
            float corr = __expf(mrow[u] - mnew);
            float p0 = __expf(S[u][0] - mnew);
            float p1 = __expf(S[u][1] - mnew);
            float p2 = __expf(S[u][2] - mnew);
            float p3 = __expf(S[u][3] - mnew);
            float rs = (p0 + p1) + (p2 + p3);
#pragma unroll
            for (int o = 8; o >= 1; o >>= 1)
                rs += __shfl_xor_sync(0xffffffffu, rs, o, 16);
            lsum[u] = lsum[u] * corr + rs;
            mrow[u] = mnew;
#pragma unroll
            for (int e = 0; e < 4; e++) acc[u][e] *= corr;
            S[u][0] = p0; S[u][1] = p1; S[u][2] = p2; S[u][3] = p3;
        }

        // write P transposed ([j][i]) via register transpose
#pragma unroll
        for (int e = 0; e < 4; e++) {
            float4 col = make_float4(S[0][e], S[1][e], S[2][e], S[3][e]);
            *(float4*)&PT[(tx * 4 + e) * 68 + ty * 4] = col;
        }
        __syncthreads();

        // O += P . Vj
#pragma unroll 8
        for (int j = 0; j < 64; j++) {
            float4 p4 = *(float4*)&PT[j * 68 + ty * 4];
            float4 v4 = *(float4*)&Vj[j * 64 + tx * 4];
            float pp[4] = {p4.x, p4.y, p4.z, p4.w};
            float vv[4] = {v4.x, v4.y, v4.z, v4.w};
#pragma unroll
            for (int u = 0; u < 4; u++)
#pragma unroll
                for (int e = 0; e < 4; e++) acc[u][e] += pp[u] * vv[e];
        }
    }

    int b = bh / NHEAD;
    int h = bh - b * NHEAD;
#pragma unroll
    for (int u = 0; u < 4; u++) {
        int gi = i0 + ty * 4 + u;
        if (gi < NTOK) {
            float inv = 1.0f / lsum[u];
            float4 o = make_float4(acc[u][0] * inv, acc[u][1] * inv,
                                   acc[u][2] * inv, acc[u][3] * inv);
            *(float4*)&d_Obuf[((size_t)b * NTOK + gi) * CDIM + h * HD + tx * 4] = o;
        }
    }
}

// ---------------------------------------------------------------------------
// Kernel 4: output projection.  out[m,c] = O[m,:] . proj_w[c,:] + proj_b[c]
// ---------------------------------------------------------------------------
__global__ void gemm_proj(const float* __restrict__ w,
                          const float* __restrict__ bias,
                          float* __restrict__ out) {
    __shared__ float As[16][64];
    __shared__ float Bs[16][64];
    int tid = threadIdx.x;
    int ty = tid >> 4, tx = tid & 15;
    int m0 = blockIdx.y * 64;
    int c0 = blockIdx.x * 64;   // 0..767

    float acc[4][4];
#pragma unroll
    for (int u = 0; u < 4; u++)
#pragma unroll
        for (int e = 0; e < 4; e++) acc[u][e] = 0.0f;

    int lr = tid >> 2;
    int lq = (tid & 3) * 4;
    const float* arow = d_Obuf + (size_t)(m0 + lr) * CDIM;
    const float* wrow = w + (size_t)(c0 + lr) * CDIM;

    for (int kt = 0; kt < CDIM; kt += 16) {
        float4 av = *(const float4*)(arow + kt + lq);
        float4 wv = *(const float4*)(wrow + kt + lq);
        As[lq + 0][lr] = av.x; As[lq + 1][lr] = av.y;
        As[lq + 2][lr] = av.z; As[lq + 3][lr] = av.w;
        Bs[lq + 0][lr] = wv.x; Bs[lq + 1][lr] = wv.y;
        Bs[lq + 2][lr] = wv.z; Bs[lq + 3][lr] = wv.w;
        __syncthreads();
#pragma unroll
        for (int k = 0; k < 16; k++) {
            float4 a4 = *(float4*)&As[k][ty * 4];
            float4 b4 = *(float4*)&Bs[k][tx * 4];
            float aa[4] = {a4.x, a4.y, a4.z, a4.w};
            float bb[4] = {b4.x, b4.y, b4.z, b4.w};
#pragma unroll
            for (int u = 0; u < 4; u++)
#pragma unroll
                for (int e = 0; e < 4; e++) acc[u][e] += aa[u] * bb[e];
        }
        __syncthreads();
    }

    float4 bv = *(const float4*)(bias + c0 + tx * 4);
#pragma unroll
    for (int u = 0; u < 4; u++) {
        int m = m0 + ty * 4 + u;
        float4 o;
        o.x = acc[u][0] + bv.x; o.y = acc[u][1] + bv.y;
        o.z = acc[u][2] + bv.z; o.w = acc[u][3] + bv.w;
        *(float4*)&out[(size_t)m * CDIM + c0 + tx * 4] = o;
    }
}

// ---------------------------------------------------------------------------
// kernel_launch: resolve inputs BY ELEMENT COUNT (robust to metadata ordering)
// ---------------------------------------------------------------------------
extern "C" void kernel_launch(void* const* d_in, const int* in_sizes, int n_in,
                              void* d_out, int out_size) {
    const float* x = 0;
    const float* qkv_w = 0;
    const float* qkv_b = 0;
    const float* proj_w = 0;
    const float* proj_b = 0;
    for (int i = 0; i < n_in; i++) {
        switch (in_sizes[i]) {
            case 6340608: x      = (const float*)d_in[i]; break;
            case 1769472: qkv_w  = (const float*)d_in[i]; break;
            case 2304:    qkv_b  = (const float*)d_in[i]; break;
            case 589824:  proj_w = (const float*)d_in[i]; break;
            case 768:     proj_b = (const float*)d_in[i]; break;
            default: break;
        }
    }
    float* out = (float*)d_out;

    const int ATTN_SMEM = (4096 + 4096 + 4096 + 64 * 68) * 4;  // 66560 bytes
    cudaFuncSetAttribute(attn_kernel,
                         cudaFuncAttributeMaxDynamicSharedMemorySize, ATTN_SMEM);

    add_kernel<<<(NTOK * NTOK + 64 + 255) / 256, 256>>>();
    gemm_kv<<<dim3(24, 129), 256>>>(x, qkv_w, qkv_b);
    attn_kernel<<<dim3(17, BATCH * NHEAD), 256, ATTN_SMEM>>>();
    gemm_proj<<<dim3(12, 129), 256>>>(proj_w, proj_b, out);
}

// round 4
// speedup vs baseline: 1.2146x; 1.2146x over previous
#include <cuda_runtime.h>

#define BATCH 8
#define NTOK 1032
#define CDIM 768
#define NHEAD 12
#define HD 64
#define SCALE 0.125f
#define MTOT (BATCH * NTOK)   // 8256

// Scratch (static device globals; allocation-free)
__device__ float d_add[NTOK * NTOK + 64];
__device__ float d_Kbuf[BATCH * NHEAD * NTOK * HD];    // [b][h][n][d]
__device__ float d_Vbuf[BATCH * NHEAD * NTOK * HD];
__device__ float d_Obuf[MTOT * CDIM];                  // [b*n][h*64+d]

// ---------------------------------------------------------------------------
// Kernel 1: gaussian additive bias table
// ---------------------------------------------------------------------------
__global__ void add_kernel() {
    int idx = blockIdx.x * 256 + threadIdx.x;
    if (idx >= NTOK * NTOK + 64) return;
    float v = 0.0f;
    if (idx < NTOK * NTOK) {
        int i = idx / NTOK, j = idx - (idx / NTOK) * NTOK;
        if (i >= 8 && j >= 8) {
            int p = i - 8, q = j - 8;
            int dr = (p >> 5) - (q >> 5);
            int dc = (p & 31) - (q & 31);
            v = __expf(-0.02f * (float)(dr * dr + dc * dc));
        }
    }
    d_add[idx] = v;
}

// ---------------------------------------------------------------------------
// Kernel 2: KV GEMM, 128x128 tile, 8x8 per thread.
// out[m, c] = x[m,:] . qkv_w[768+c,:] + qkv_b[768+c], scatter to K/V bufs.
// ---------------------------------------------------------------------------
__global__ __launch_bounds__(256, 2)
void gemm_kv(const float* __restrict__ x,
             const float* __restrict__ w,
             const float* __restrict__ bias) {
    __shared__ float As[16][128];
    __shared__ float Bs[16][128];
    int tid = threadIdx.x;
    int ty = tid >> 4, tx = tid & 15;
    int m0 = blockIdx.y * 128;
    int c0 = blockIdx.x * 128;       // [0,1536)

    float acc[8][8];
#pragma unroll
    for (int u = 0; u < 8; u++)
#pragma unroll
        for (int e = 0; e < 8; e++) acc[u][e] = 0.0f;

    int lr = tid >> 1;               // 0..127
    int lq = (tid & 1) * 8;          // 0 or 8
    int mload = m0 + lr; if (mload > MTOT - 1) mload = MTOT - 1;
    const float* xrow = x + (size_t)mload * CDIM;
    const float* wrow = w + (size_t)(CDIM + c0 + lr) * CDIM;

    for (int kt = 0; kt < CDIM; kt += 16) {
        float4 a0 = *(const float4*)(xrow + kt + lq);
        float4 a1 = *(const float4*)(xrow + kt + lq + 4);
        float4 b0 = *(const float4*)(wrow + kt + lq);
        float4 b1 = *(const float4*)(wrow + kt + lq + 4);
        As[lq + 0][lr] = a0.x; As[lq + 1][lr] = a0.y;
        As[lq + 2][lr] = a0.z; As[lq + 3][lr] = a0.w;
        As[lq + 4][lr] = a1.x; As[lq + 5][lr] = a1.y;
        As[lq + 6][lr] = a1.z; As[lq + 7][lr] = a1.w;
        Bs[lq + 0][lr] = b0.x; Bs[lq + 1][lr] = b0.y;
        Bs[lq + 2][lr] = b0.z; Bs[lq + 3][lr] = b0.w;
        Bs[lq + 4][lr] = b1.x; Bs[lq + 5][lr] = b1.y;
        Bs[lq + 6][lr] = b1.z; Bs[lq + 7][lr] = b1.w;
        __syncthreads();
#pragma unroll
        for (int k = 0; k < 16; k++) {
            float4 x0 = *(float4*)&As[k][ty * 8];
            float4 x1 = *(float4*)&As[k][ty * 8 + 4];
            float4 y0 = *(float4*)&Bs[k][tx * 8];
            float4 y1 = *(float4*)&Bs[k][tx * 8 + 4];
            float aa[8] = {x0.x, x0.y, x0.z, x0.w, x1.x, x1.y, x1.z, x1.w};
            float bb[8] = {y0.x, y0.y, y0.z, y0.w, y1.x, y1.y, y1.z, y1.w};
#pragma unroll
            for (int u = 0; u < 8; u++)
#pragma unroll
                for (int e = 0; e < 8; e++) acc[u][e] += aa[u] * bb[e];
        }
        __syncthreads();
    }

    int c = c0 + tx * 8;                       // 8 cols, same head (8|64)
    float4 bv0 = *(const float4*)(bias + CDIM + c);
    float4 bv1 = *(const float4*)(bias + CDIM + c + 4);
    bool isK = (c0 < CDIM);                    // 128|768 -> whole tile one side
    float* dst = isK ? d_Kbuf : d_Vbuf;
    int cc = isK ? c : (c - CDIM);
    int h = cc >> 6;
    int cm = cc & 63;
#pragma unroll
    for (int u = 0; u < 8; u++) {
        int m = m0 + ty * 8 + u;
        if (m < MTOT) {
            int b = m / NTOK;
            int n = m - b * NTOK;
            size_t base = (((size_t)b * NHEAD + h) * NTOK + n) * HD + cm;
            float4 o0 = make_float4(acc[u][0] + bv0.x, acc[u][1] + bv0.y,
                                    acc[u][2] + bv0.z, acc[u][3] + bv0.w);
            float4 o1 = make_float4(acc[u][4] + bv1.x, acc[u][5] + bv1.y,
                                    acc[u][6] + bv1.z, acc[u][7] + bv1.w);
            *(float4*)&dst[base] = o0;
            *(float4*)&dst[base + 4] = o1;
        }
    }
}

// ---------------------------------------------------------------------------
// Kernel 3: flash attention, 128 i-rows x 64 j-cols per tile, 8x4 per thread.
// ---------------------------------------------------------------------------
#define KI_PITCH 128
#define VJ_PITCH 68
#define PT_PITCH 132
#define ATTN_SMEM_FLOATS (64 * KI_PITCH + 64 * 64 + 64 * VJ_PITCH + 64 * PT_PITCH)

__global__ __launch_bounds__(256, 2)
void attn_kernel() {
    extern __shared__ float sm[];
    float* KiT = sm;                           // [d=64][i=128]
    float* KjT = sm + 64 * KI_PITCH;           // [d=64][j=64]
    float* Vj  = KjT + 64 * 64;                // [j=64][d=64] pitch 68
    float* PT  = Vj + 64 * VJ_PITCH;           // [j=64][i=128] pitch 132

    int tid = threadIdx.x;
    int ty = tid >> 4, tx = tid & 15;
    int i0 = blockIdx.x * 128;
    int bh = blockIdx.y;
    const float* Kbh = d_Kbuf + (size_t)bh * NTOK * HD;
    const float* Vbh = d_Vbuf + (size_t)bh * NTOK * HD;

    {   // load Ki transposed: tok = tid&127 (lane-distinct -> conflict-free STS)
        int tok = tid & 127;
        int chunk = tid >> 7;                  // 0..1 -> d base 0/32
        int gi = i0 + tok; if (gi > NTOK - 1) gi = NTOK - 1;
        const float* base = Kbh + (size_t)gi * HD + chunk * 32;
#pragma unroll
        for (int s = 0; s < 8; s++) {
            float4 v = *(const float4*)(base + s * 4);
            int d = chunk * 32 + s * 4;
            KiT[(d + 0) * KI_PITCH + tok] = v.x;
            KiT[(d + 1) * KI_PITCH + tok] = v.y;
            KiT[(d + 2) * KI_PITCH + tok] = v.z;
            KiT[(d + 3) * KI_PITCH + tok] = v.w;
        }
    }

    float mrow[8], lsum[8], acc[8][4];
#pragma unroll
    for (int u = 0; u < 8; u++) {
        mrow[u] = -1e30f; lsum[u] = 0.0f;
#pragma unroll
        for (int e = 0; e < 4; e++) acc[u][e] = 0.0f;
    }

    const int NJT = (NTOK + 63) / 64;          // 17
    for (int jt = 0; jt < NJT; jt++) {
        int j0 = jt * 64;
        __syncthreads();
        {   // Kj transposed: tok = tid&63, chunk = tid>>6 -> d base chunk*16
            int tok = tid & 63;
            int chunk = tid >> 6;
            int gj = j0 + tok;
            bool ok = (gj < NTOK);
            const float* kb = Kbh + (size_t)(ok ? gj : 0) * HD + chunk * 16;
#pragma unroll
            for (int s = 0; s < 4; s++) {
                float4 v = ok ? *(const float4*)(kb + s * 4)
                              : make_float4(0, 0, 0, 0);
                int d = chunk * 16 + s * 4;
                KjT[(d + 0) * 64 + tok] = v.x;
                KjT[(d + 1) * 64 + tok] = v.y;
                KjT[(d + 2) * 64 + tok] = v.z;
                KjT[(d + 3) * 64 + tok] = v.w;
            }
        }
        {   // Vj row-major: 16 lanes per row, perfectly coalesced LDG
#pragma unroll
            for (int p = 0; p < 4; p++) {
                int row = p * 16 + (tid >> 4);
                int gj = j0 + row;
                float4 v = (gj < NTOK)
                    ? *(const float4*)(Vbh + (size_t)gj * HD + (tid & 15) * 4)
                    : make_float4(0, 0, 0, 0);
                *(float4*)&Vj[row * VJ_PITCH + (tid & 15) * 4] = v;
            }
        }
        __syncthreads();

        float S[8][4];
#pragma unroll
        for (int u = 0; u < 8; u++)
#pragma unroll
            for (int e = 0; e < 4; e++) S[u][e] = 0.0f;

#pragma unroll 8
        for (int k = 0; k < 64; k++) {
            float4 x0 = *(float4*)&KiT[k * KI_PITCH + ty * 8];
            float4 x1 = *(float4*)&KiT[k * KI_PITCH + ty * 8 + 4];
            float4 y0 = *(float4*)&KjT[k * 64 + tx * 4];
            float aa[8] = {x0.x, x0.y, x0.z, x0.w, x1.x, x1.y, x1.z, x1.w};
            float bb[4] = {y0.x, y0.y, y0.z, y0.w};
#pragma unroll
            for (int u = 0; u < 8; u++)
#pragma unroll
                for (int e = 0; e < 4; e++) S[u][e] += aa[u] * bb[e];
        }

        int jcol = j0 + tx * 4;
#pragma unroll
        for (int u = 0; u < 8; u++) {
            int gi = i0 + ty * 8 + u;
            int ai = (gi < NTOK) ? gi : (NTOK - 1);
            float4 a4 = *(const float4*)(d_add + (size_t)ai * NTOK + jcol);
            float ad[4] = {a4.x, a4.y, a4.z, a4.w};
#pragma unroll
            for (int e = 0; e < 4; e++) {
                float s = S[u][e] * SCALE + ad[e];
                S[u][e] = (jcol + e < NTOK) ? s : -1e30f;
            }
            float mt = fmaxf(fmaxf(S[u][0], S[u][1]), fmaxf(S[u][2], S[u][3]));
#pragma unroll
            for (int o = 8; o >= 1; o >>= 1)
                mt = fmaxf(mt, __shfl_xor_sync(0xffffffffu, mt, o, 16));
            float mnew = fmaxf(mrow[u], mt);
            float corr = __expf(mrow[u] - mnew);
            float p0 = __expf(S[u][0] - mnew);
            float p1 = __expf(S[u][1] - mnew);
            float p2 = __expf(S[u][2] - mnew);
            float p3 = __expf(S[u][3] - mnew);
            float rs = (p0 + p1) + (p2 + p3);
#pragma unroll
            for (int o = 8; o >= 1; o >>= 1)
                rs += __shfl_xor_sync(0xffffffffu, rs, o, 16);
            lsum[u] = lsum[u] * corr + rs;
            mrow[u] = mnew;
#pragma unroll
            for (int e = 0; e < 4; e++) acc[u][e] *= corr;
            S[u][0] = p0; S[u][1] = p1; S[u][2] = p2; S[u][3] = p3;
        }

        // P transposed [j][i] via register transpose (STS.128 x2 per col)
#pragma unroll
        for (int e = 0; e < 4; e++) {
            float4 c0v = make_float4(S[0][e], S[1][e], S[2][e], S[3][e]);
            float4 c1v = make_float4(S[4][e], S[5][e], S[6][e], S[7][e]);
            *(float4*)&PT[(tx * 4 + e) * PT_PITCH + ty * 8] = c0v;
            *(float4*)&PT[(tx * 4 + e) * PT_PITCH + ty * 8 + 4] = c1v;
        }
        __syncthreads();

        // O += P . Vj
#pragma unroll 8
        for (int j = 0; j < 64; j++) {
            float4 x0 = *(float4*)&PT[j * PT_PITCH + ty * 8];
            float4 x1 = *(float4*)&PT[j * PT_PITCH + ty * 8 + 4];
            float4 y0 = *(float4*)&Vj[j * VJ_PITCH + tx * 4];
            float pp[8] = {x0.x, x0.y, x0.z, x0.w, x1.x, x1.y, x1.z, x1.w};
            float vv[4] = {y0.x, y0.y, y0.z, y0.w};
#pragma unroll
            for (int u = 0; u < 8; u++)
#pragma unroll
                for (int e = 0; e < 4; e++) acc[u][e] += pp[u] * vv[e];
        }
    }

    int b = bh / NHEAD;
    int h = bh - b * NHEAD;
#pragma unroll
    for (int u = 0; u < 8; u++) {
        int gi = i0 + ty * 8 + u;
        if (gi < NTOK) {
            float inv = 1.0f / lsum[u];
            float4 o = make_float4(acc[u][0] * inv, acc[u][1] * inv,
                                   acc[u][2] * inv, acc[u][3] * inv);
            *(float4*)&d_Obuf[((size_t)b * NTOK + gi) * CDIM + h * HD + tx * 4] = o;
        }
    }
}

// ---------------------------------------------------------------------------
// Kernel 4: output projection, 128x128 tile, 8x8 per thread.
// ---------------------------------------------------------------------------
__global__ __launch_bounds__(256, 2)
void gemm_proj(const float* __restrict__ w,
               const float* __restrict__ bias,
               float* __restrict__ out) {
    __shared__ float As[16][128];
    __shared__ float Bs[16][128];
    int tid = threadIdx.x;
    int ty = tid >> 4, tx = tid & 15;
    int m0 = blockIdx.y * 128;
    int c0 = blockIdx.x * 128;

    float acc[8][8];
#pragma unroll
    for (int u = 0; u < 8; u++)
#pragma unroll
        for (int e = 0; e < 8; e++) acc[u][e] = 0.0f;

    int lr = tid >> 1;
    int lq = (tid & 1) * 8;
    int mload = m0 + lr; if (mload > MTOT - 1) mload = MTOT - 1;
    const float* arow = d_Obuf + (size_t)mload * CDIM;
    const float* wrow = w + (size_t)(c0 + lr) * CDIM;

    for (int kt = 0; kt < CDIM; kt += 16) {
        float4 a0 = *(const float4*)(arow + kt + lq);
        float4 a1 = *(const float4*)(arow + kt + lq + 4);
        float4 b0 = *(const float4*)(wrow + kt + lq);
        float4 b1 = *(const float4*)(wrow + kt + lq + 4);
        As[lq + 0][lr] = a0.x; As[lq + 1][lr] = a0.y;
        As[lq + 2][lr] = a0.z; As[lq + 3][lr] = a0.w;
        As[lq + 4][lr] = a1.x; As[lq + 5][lr] = a1.y;
        As[lq + 6][lr] = a1.z; As[lq + 7][lr] = a1.w;
        Bs[lq + 0][lr] = b0.x; Bs[lq + 1][lr] = b0.y;
        Bs[lq + 2][lr] = b0.z; Bs[lq + 3][lr] = b0.w;
        Bs[lq + 4][lr] = b1.x; Bs[lq + 5][lr] = b1.y;
        Bs[lq + 6][lr] = b1.z; Bs[lq + 7][lr] = b1.w;
        __syncthreads();
#pragma unroll
        for (int k = 0; k < 16; k++) {
            float4 x0 = *(float4*)&As[k][ty * 8];
            float4 x1 = *(float4*)&As[k][ty * 8 + 4];
            float4 y0 = *(float4*)&Bs[k][tx * 8];
            float4 y1 = *(float4*)&Bs[k][tx * 8 + 4];
            float aa[8] = {x0.x, x0.y, x0.z, x0.w, x1.x, x1.y, x1.z, x1.w};
            float bb[8] = {y0.x, y0.y, y0.z, y0.w, y1.x, y1.y, y1.z, y1.w};
#pragma unroll
            for (int u = 0; u < 8; u++)
#pragma unroll
                for (int e = 0; e < 8; e++) acc[u][e] += aa[u] * bb[e];
        }
        __syncthreads();
    }

    int c = c0 + tx * 8;
    float4 bv0 = *(const float4*)(bias + c);
    float4 bv1 = *(const float4*)(bias + c + 4);
#pragma unroll
    for (int u = 0; u < 8; u++) {
        int m = m0 + ty * 8 + u;
        if (m < MTOT) {
            float4 o0 = make_float4(acc[u][0] + bv0.x, acc[u][1] + bv0.y,
                                    acc[u][2] + bv0.z, acc[u][3] + bv0.w);
            float4 o1 = make_float4(acc[u][4] + bv1.x, acc[u][5] + bv1.y,
                                    acc[u][6] + bv1.z, acc[u][7] + bv1.w);
            *(float4*)&out[(size_t)m * CDIM + c] = o0;
            *(float4*)&out[(size_t)m * CDIM + c + 4] = o1;
        }
    }
}

// ---------------------------------------------------------------------------
extern "C" void kernel_launch(void* const* d_in, const int* in_sizes, int n_in,
                              void* d_out, int out_size) {
    const float* x = 0;
    const float* qkv_w = 0;
    const float* qkv_b = 0;
    const float* proj_w = 0;
    const float* proj_b = 0;
    for (int i = 0; i < n_in; i++) {
        switch (in_sizes[i]) {
            case 6340608: x      = (const float*)d_in[i]; break;
            case 1769472: qkv_w  = (const float*)d_in[i]; break;
            case 2304:    qkv_b  = (const float*)d_in[i]; break;
            case 589824:  proj_w = (const float*)d_in[i]; break;
            case 768:     proj_b = (const float*)d_in[i]; break;
            default: break;
        }
    }
    float* out = (float*)d_out;

    const int ATTN_SMEM = ATTN_SMEM_FLOATS * 4;   // 100352 bytes
    cudaFuncSetAttribute(attn_kernel,
                         cudaFuncAttributeMaxDynamicSharedMemorySize, ATTN_SMEM);

    add_kernel<<<(NTOK * NTOK + 64 + 255) / 256, 256>>>();
    gemm_kv<<<dim3(12, 65), 256>>>(x, qkv_w, qkv_b);
    attn_kernel<<<dim3(9, BATCH * NHEAD), 256, ATTN_SMEM>>>();
    gemm_proj<<<dim3(6, 65), 256>>>(proj_w, proj_b, out);
}

// round 10
// speedup vs baseline: 1.4782x; 1.2170x over previous
#include <cuda_runtime.h>
#include <cuda_bf16.h>
#include <cstdint>

#define BATCH 8
#define NTOK 1032
#define CDIM 768
#define NHEAD 12
#define HD 64
#define SCALE 0.125f
#define MTOT (BATCH * NTOK)   // 8256

// ---------------- scratch (static device globals; allocation-free) ----------
__device__ float d_add[NTOK * NTOK + 64];
__device__ float d_Kbuf[BATCH * NHEAD * NTOK * HD];
__device__ float d_Vbuf[BATCH * NHEAD * NTOK * HD];

__device__ __align__(16) __nv_bfloat16 d_xhi[MTOT * CDIM];
__device__ __align__(16) __nv_bfloat16 d_xlo[MTOT * CDIM];
__device__ __align__(16) __nv_bfloat16 d_wkv_hi[2 * CDIM * CDIM];
__device__ __align__(16) __nv_bfloat16 d_wkv_lo[2 * CDIM * CDIM];
__device__ __align__(16) __nv_bfloat16 d_wp_hi[CDIM * CDIM];
__device__ __align__(16) __nv_bfloat16 d_wp_lo[CDIM * CDIM];
__device__ __align__(16) __nv_bfloat16 d_ohi[MTOT * CDIM];   // written by attn
__device__ __align__(16) __nv_bfloat16 d_olo[MTOT * CDIM];

// ---------------- helpers ----------------------------------------------------
__device__ __forceinline__ uint32_t swz(uint32_t o) { return o ^ ((o >> 3) & 0x70); }

__device__ __forceinline__ void mma_bf16(float* c, const uint32_t* a,
                                         uint32_t b0, uint32_t b1) {
    asm volatile(
        "mma.sync.aligned.m16n8k16.row.col.f32.bf16.bf16.f32 "
        "{%0,%1,%2,%3}, {%4,%5,%6,%7}, {%8,%9}, {%0,%1,%2,%3};"
        : "+f"(c[0]), "+f"(c[1]), "+f"(c[2]), "+f"(c[3])
        : "r"(a[0]), "r"(a[1]), "r"(a[2]), "r"(a[3]), "r"(b0), "r"(b1));
}

// ---------------------------------------------------------------------------
// Kernel 1: gaussian additive bias table
// ---------------------------------------------------------------------------
__global__ void add_kernel() {
    int idx = blockIdx.x * 256 + threadIdx.x;
    if (idx >= NTOK * NTOK + 64) return;
    float v = 0.0f;
    if (idx < NTOK * NTOK) {
        int i = idx / NTOK, j = idx - (idx / NTOK) * NTOK;
        if (i >= 8 && j >= 8) {
            int p = i - 8, q = j - 8;
            int dr = (p >> 5) - (q >> 5);
            int dc = (p & 31) - (q & 31);
            v = __expf(-0.02f * (float)(dr * dr + dc * dc));
        }
    }
    d_add[idx] = v;
}

// ---------------------------------------------------------------------------
// split: fp32 -> bf16 hi + lo.  src is ALWAYS a harness device pointer.
// Destination selected by mode INSIDE device code (never pass device symbols
// from host — host sees the .bss shadow, GPU reads zeros via ATS).
// ---------------------------------------------------------------------------
__global__ void split_kernel(const float* __restrict__ src, int n, int mode) {
    int i = blockIdx.x * 256 + threadIdx.x;
    if (i >= n) return;
    float v = src[i];
    __nv_bfloat16 h = __float2bfloat16(v);
    __nv_bfloat16 l = __float2bfloat16(v - __bfloat162float(h));
    __nv_bfloat16 *dh, *dl;
    if (mode == 0)      { dh = d_xhi;    dl = d_xlo;    }
    else if (mode == 1) { dh = d_wkv_hi; dl = d_wkv_lo; }
    else                { dh = d_wp_hi;  dl = d_wp_lo;  }
    dh[i] = h; dl[i] = l;
}

// ---------------------------------------------------------------------------
// mma.sync GEMM, direct-LDS fragments, bf16-split 3-product.
// MODE 0: A = O splits,  B = proj_w splits -> out (+proj_b)
// MODE 1: A = x splits,  B = w_kv splits   -> scatter K/V (+qkv_b[768:])
// CTA 128x128, 8 warps (32m x 64n), K-chunk 64, SW128 smem tiles.
// ---------------------------------------------------------------------------
#define GM_SMEM_BYTES (4 * 16384)

template <int MODE>
__global__ __launch_bounds__(256)
void gemm_mma(const float* __restrict__ bias, float* __restrict__ out) {
    extern __shared__ char smem[];
    const int tid = threadIdx.x;
    const int wid = tid >> 5;
    const int lane = tid & 31;
    const int g = lane >> 2, t = lane & 3;

    const int m0 = blockIdx.y * 128;
    const int c0 = blockIdx.x * 128;
    const int wm = (wid & 3) * 32;
    const int wn = (wid >> 2) * 64;

    const __nv_bfloat16* Ahi = (MODE == 0) ? d_ohi : d_xhi;
    const __nv_bfloat16* Alo = (MODE == 0) ? d_olo : d_xlo;
    const __nv_bfloat16* Bhi = (MODE == 0) ? d_wp_hi : d_wkv_hi;
    const __nv_bfloat16* Blo = (MODE == 0) ? d_wp_lo : d_wkv_lo;

    float C[2][8][4];
#pragma unroll
    for (int mt = 0; mt < 2; mt++)
#pragma unroll
        for (int nt = 0; nt < 8; nt++)
#pragma unroll
            for (int e = 0; e < 4; e++) C[mt][nt][e] = 0.0f;

    const char* sA_hi = smem;
    const char* sA_lo = smem + 16384;
    const char* sB_hi = smem + 32768;
    const char* sB_lo = smem + 49152;

    for (int kc = 0; kc < CDIM / 64; kc++) {
        const int kt = kc * 64;
        for (int seg = tid; seg < 4096; seg += 256) {
            int buf = seg >> 10;
            int idx = seg & 1023;
            int row = idx >> 3;
            int s = idx & 7;
            const __nv_bfloat16* src;
            size_t grow;
            if (buf < 2) {
                int gg = m0 + row; if (gg > MTOT - 1) gg = MTOT - 1;
                grow = (size_t)gg;
                src = (buf == 0) ? Ahi : Alo;
            } else {
                grow = (size_t)(c0 + row);
                src = (buf == 2) ? Bhi : Blo;
            }
            uint4 v = *(const uint4*)(src + grow * CDIM + kt + s * 8);
            *(uint4*)(smem + buf * 16384 + swz(row * 128 + s * 16)) = v;
        }
        __syncthreads();

#pragma unroll
        for (int ks = 0; ks < 4; ks++) {
            const uint32_t kb = ks * 32 + t * 4;
            uint32_t ah[2][4], al[2][4];
#pragma unroll
            for (int mt = 0; mt < 2; mt++) {
                uint32_t r0 = (uint32_t)(wm + mt * 16 + g) * 128;
                uint32_t r8 = r0 + 8 * 128;
                ah[mt][0] = *(const uint32_t*)(sA_hi + swz(r0 + kb));
                ah[mt][1] = *(const uint32_t*)(sA_hi + swz(r8 + kb));
                ah[mt][2] = *(const uint32_t*)(sA_hi + swz(r0 + kb + 16));
                ah[mt][3] = *(const uint32_t*)(sA_hi + swz(r8 + kb + 16));
                al[mt][0] = *(const uint32_t*)(sA_lo + swz(r0 + kb));
                al[mt][1] = *(const uint32_t*)(sA_lo + swz(r8 + kb));
                al[mt][2] = *(const uint32_t*)(sA_lo + swz(r0 + kb + 16));
                al[mt][3] = *(const uint32_t*)(sA_lo + swz(r8 + kb + 16));
            }
#pragma unroll
            for (int nt = 0; nt < 8; nt++) {
                uint32_t br = (uint32_t)(wn + nt * 8 + g) * 128;
                uint32_t bh0 = *(const uint32_t*)(sB_hi + swz(br + kb));
                uint32_t bh1 = *(const uint32_t*)(sB_hi + swz(br + kb + 16));
                uint32_t bl0 = *(const uint32_t*)(sB_lo + swz(br + kb));
                uint32_t bl1 = *(const uint32_t*)(sB_lo + swz(br + kb + 16));
#pragma unroll
                for (int mt = 0; mt < 2; mt++) {
                    mma_bf16(C[mt][nt], ah[mt], bh0, bh1);
                    mma_bf16(C[mt][nt], ah[mt], bl0, bl1);
                    mma_bf16(C[mt][nt], al[mt], bh0, bh1);
                }
            }
        }
        __syncthreads();
    }

#pragma unroll
    for (int mt = 0; mt < 2; mt++) {
#pragma unroll
        for (int nt = 0; nt < 8; nt++) {
            int col = c0 + wn + nt * 8 + t * 2;
            float bx = bias[col], by = bias[col + 1];
#pragma unroll
            for (int half = 0; half < 2; half++) {
                int row = m0 + wm + mt * 16 + g + half * 8;
                if (row >= MTOT) continue;
                float vx = C[mt][nt][half * 2 + 0] + bx;
                float vy = C[mt][nt][half * 2 + 1] + by;
                if (MODE == 0) {
                    *(float2*)&out[(size_t)row * CDIM + col] = make_float2(vx, vy);
                } else {
                    bool isK = (col < CDIM);
                    int cc = isK ? col : (col - CDIM);
                    int h = cc >> 6, d = cc & 63;
                    int b = row / NTOK, n = row - (row / NTOK) * NTOK;
                    float* dst = isK ? d_Kbuf : d_Vbuf;
                    *(float2*)&dst[(((size_t)b * NHEAD + h) * NTOK + n) * HD + d] =
                        make_float2(vx, vy);
                }
            }
        }
    }
}

// ---------------------------------------------------------------------------
// Kernel 3: flash attention (R4-proven core). Epilogue now writes bf16 hi/lo
// splits of O directly (device-side; fixes the host-symbol bug, saves a pass).
// ---------------------------------------------------------------------------
#define KI_PITCH 128
#define VJ_PITCH 68
#define PT_PITCH 132
#define ATTN_SMEM_FLOATS (64 * KI_PITCH + 64 * 64 + 64 * VJ_PITCH + 64 * PT_PITCH)

__global__ __launch_bounds__(256, 2)
void attn_kernel() {
    extern __shared__ float sm[];
    float* KiT = sm;
    float* KjT = sm + 64 * KI_PITCH;
    float* Vj  = KjT + 64 * 64;
    float* PT  = Vj + 64 * VJ_PITCH;

    int tid = threadIdx.x;
    int ty = tid >> 4, tx = tid & 15;
    int i0 = blockIdx.x * 128;
    int bh = blockIdx.y;
    const float* Kbh = d_Kbuf + (size_t)bh * NTOK * HD;
    const float* Vbh = d_Vbuf + (size_t)bh * NTOK * HD;

    {
        int tok = tid & 127;
        int chunk = tid >> 7;
        int gi = i0 + tok; if (gi > NTOK - 1) gi = NTOK - 1;
        const float* base = Kbh + (size_t)gi * HD + chunk * 32;
#pragma unroll
        for (int s = 0; s < 8; s++) {
            float4 v = *(const float4*)(base + s * 4);
            int d = chunk * 32 + s * 4;
            KiT[(d + 0) * KI_PITCH + tok] = v.x;
            KiT[(d + 1) * KI_PITCH + tok] = v.y;
            KiT[(d + 2) * KI_PITCH + tok] = v.z;
            KiT[(d + 3) * KI_PITCH + tok] = v.w;
        }
    }

    float mrow[8], lsum[8], acc[8][4];
#pragma unroll
    for (int u = 0; u < 8; u++) {
        mrow[u] = -1e30f; lsum[u] = 0.0f;
#pragma unroll
        for (int e = 0; e < 4; e++) acc[u][e] = 0.0f;
    }

    const int NJT = (NTOK + 63) / 64;
    for (int jt = 0; jt < NJT; jt++) {
        int j0 = jt * 64;
        __syncthreads();
        {
            int tok = tid & 63;
            int chunk = tid >> 6;
            int gj = j0 + tok;
            bool ok = (gj < NTOK);
            const float* kb = Kbh + (size_t)(ok ? gj : 0) * HD + chunk * 16;
#pragma unroll
            for (int s = 0; s < 4; s++) {
                float4 v = ok ? *(const float4*)(kb + s * 4)
                              : make_float4(0, 0, 0, 0);
                int d = chunk * 16 + s * 4;
                KjT[(d + 0) * 64 + tok] = v.x;
                KjT[(d + 1) * 64 + tok] = v.y;
                KjT[(d + 2) * 64 + tok] = v.z;
                KjT[(d + 3) * 64 + tok] = v.w;
            }
        }
        {
#pragma unroll
            for (int p = 0; p < 4; p++) {
                int row = p * 16 + (tid >> 4);
                int gj = j0 + row;
                float4 v = (gj < NTOK)
                    ? *(const float4*)(Vbh + (size_t)gj * HD + (tid & 15) * 4)
                    : make_float4(0, 0, 0, 0);
                *(float4*)&Vj[row * VJ_PITCH + (tid & 15) * 4] = v;
            }
        }
        __syncthreads();

        float S[8][4];
#pragma unroll
        for (int u = 0; u < 8; u++)
#pragma unroll
            for (int e = 0; e < 4; e++) S[u][e] = 0.0f;

#pragma unroll 8
        for (int k = 0; k < 64; k++) {
            float4 x0 = *(float4*)&KiT[k * KI_PITCH + ty * 8];
            float4 x1 = *(float4*)&KiT[k * KI_PITCH + ty * 8 + 4];
            float4 y0 = *(float4*)&KjT[k * 64 + tx * 4];
            float aa[8] = {x0.x, x0.y, x0.z, x0.w, x1.x, x1.y, x1.z, x1.w};
            float bb[4] = {y0.x, y0.y, y0.z, y0.w};
#pragma unroll
            for (int u = 0; u < 8; u++)
#pragma unroll
                for (int e = 0; e < 4; e++) S[u][e] += aa[u] * bb[e];
        }

        int jcol = j0 + tx * 4;
#pragma unroll
        for (int u = 0; u < 8; u++) {
            int gi = i0 + ty * 8 + u;
            int ai = (gi < NTOK) ? gi : (NTOK - 1);
            float4 a4 = *(const float4*)(d_add + (size_t)ai * NTOK + jcol);
            float ad[4] = {a4.x, a4.y, a4.z, a4.w};
#pragma unroll
            for (int e = 0; e < 4; e++) {
                float s = S[u][e] * SCALE + ad[e];
                S[u][e] = (jcol + e < NTOK) ? s : -1e30f;
            }
            float mt = fmaxf(fmaxf(S[u][0], S[u][1]), fmaxf(S[u][2], S[u][3]));
#pragma unroll
            for (int o = 8; o >= 1; o >>= 1)
                mt = fmaxf(mt, __shfl_xor_sync(0xffffffffu, mt, o, 16));
            float mnew = fmaxf(mrow[u], mt);
            float corr = __expf(mrow[u] - mnew);
            float p0 = __expf(S[u][0] - mnew);
            float p1 = __expf(S[u][1] - mnew);
            float p2 = __expf(S[u][2] - mnew);
            float p3 = __expf(S[u][3] - mnew);
            float rs = (p0 + p1) + (p2 + p3);
#pragma unroll
            for (int o = 8; o >= 1; o >>= 1)
                rs += __shfl_xor_sync(0xffffffffu, rs, o, 16);
            lsum[u] = lsum[u] * corr + rs;
            mrow[u] = mnew;
#pragma unroll
            for (int e = 0; e < 4; e++) acc[u][e] *= corr;
            S[u][0] = p0; S[u][1] = p1; S[u][2] = p2; S[u][3] = p3;
        }

#pragma unroll
        for (int e = 0; e < 4; e++) {
            float4 c0v = make_float4(S[0][e], S[1][e], S[2][e], S[3][e]);
            float4 c1v = make_float4(S[4][e], S[5][e], S[6][e], S[7][e]);
            *(float4*)&PT[(tx * 4 + e) * PT_PITCH + ty * 8] = c0v;
            *(float4*)&PT[(tx * 4 + e) * PT_PITCH + ty * 8 + 4] = c1v;
        }
        __syncthreads();

#pragma unroll 8
        for (int j = 0; j < 64; j++) {
            float4 x0 = *(float4*)&PT[j * PT_PITCH + ty * 8];
            float4 x1 = *(float4*)&PT[j * PT_PITCH + ty * 8 + 4];
            float4 y0 = *(float4*)&Vj[j * VJ_PITCH + tx * 4];
            float pp[8] = {x0.x, x0.y, x0.z, x0.w, x1.x, x1.y, x1.z, x1.w};
            float vv[4] = {y0.x, y0.y, y0.z, y0.w};
#pragma unroll
            for (int u = 0; u < 8; u++)
#pragma unroll
                for (int e = 0; e < 4; e++) acc[u][e] += pp[u] * vv[e];
        }
    }

    int b = bh / NHEAD;
    int h = bh - b * NHEAD;
#pragma unroll
    for (int u = 0; u < 8; u++) {
        int gi = i0 + ty * 8 + u;
        if (gi < NTOK) {
            float inv = 1.0f / lsum[u];
            float v0 = acc[u][0] * inv, v1 = acc[u][1] * inv;
            float v2 = acc[u][2] * inv, v3 = acc[u][3] * inv;
            __nv_bfloat16 h0 = __float2bfloat16(v0), h1 = __float2bfloat16(v1);
            __nv_bfloat16 h2 = __float2bfloat16(v2), h3 = __float2bfloat16(v3);
            __nv_bfloat16 l0 = __float2bfloat16(v0 - __bfloat162float(h0));
            __nv_bfloat16 l1 = __float2bfloat16(v1 - __bfloat162float(h1));
            __nv_bfloat16 l2 = __float2bfloat16(v2 - __bfloat162float(h2));
            __nv_bfloat16 l3 = __float2bfloat16(v3 - __bfloat162float(h3));
            size_t base = ((size_t)b * NTOK + gi) * CDIM + h * HD + tx * 4;
            *(__nv_bfloat162*)&d_ohi[base]     = __nv_bfloat162(h0, h1);
            *(__nv_bfloat162*)&d_ohi[base + 2] = __nv_bfloat162(h2, h3);
            *(__nv_bfloat162*)&d_olo[base]     = __nv_bfloat162(l0, l1);
            *(__nv_bfloat162*)&d_olo[base + 2] = __nv_bfloat162(l2, l3);
        }
    }
}

// ---------------------------------------------------------------------------
extern "C" void kernel_launch(void* const* d_in, const int* in_sizes, int n_in,
                              void* d_out, int out_size) {
    const float* x = 0;
    const float* qkv_w = 0;
    const float* qkv_b = 0;
    const float* proj_w = 0;
    const float* proj_b = 0;
    for (int i = 0; i < n_in; i++) {
        switch (in_sizes[i]) {
            case 6340608: x      = (const float*)d_in[i]; break;
            case 1769472: qkv_w  = (const float*)d_in[i]; break;
            case 2304:    qkv_b  = (const float*)d_in[i]; break;
            case 589824:  proj_w = (const float*)d_in[i]; break;
            case 768:     proj_b = (const float*)d_in[i]; break;
            default: break;
        }
    }
    float* out = (float*)d_out;

    const int ATTN_SMEM = ATTN_SMEM_FLOATS * 4;
    cudaFuncSetAttribute(attn_kernel,
                         cudaFuncAttributeMaxDynamicSharedMemorySize, ATTN_SMEM);
    cudaFuncSetAttribute(gemm_mma<0>,
                         cudaFuncAttributeMaxDynamicSharedMemorySize, GM_SMEM_BYTES);
    cudaFuncSetAttribute(gemm_mma<1>,
                         cudaFuncAttributeMaxDynamicSharedMemorySize, GM_SMEM_BYTES);

    add_kernel<<<(NTOK * NTOK + 64 + 255) / 256, 256>>>();

    const int NX = MTOT * CDIM;          // 6,340,608
    const int NWKV = 2 * CDIM * CDIM;    // 1,179,648
    const int NWP = CDIM * CDIM;         // 589,824
    split_kernel<<<(NX + 255) / 256, 256>>>(x, NX, 0);
    split_kernel<<<(NWKV + 255) / 256, 256>>>(qkv_w + (size_t)CDIM * CDIM, NWKV, 1);
    split_kernel<<<(NWP + 255) / 256, 256>>>(proj_w, NWP, 2);

    gemm_mma<1><<<dim3(12, 65), 256, GM_SMEM_BYTES>>>(qkv_b + CDIM, nullptr);

    attn_kernel<<<dim3(9, BATCH * NHEAD), 256, ATTN_SMEM>>>();

    gemm_mma<0><<<dim3(6, 65), 256, GM_SMEM_BYTES>>>(proj_b, out);
}

// round 11
// speedup vs baseline: 2.1354x; 1.4446x over previous
#include <cuda_runtime.h>
#include <cuda_bf16.h>
#include <cstdint>

#define BATCH 8
#define NTOK 1032
#define CDIM 768
#define NHEAD 12
#define HD 64
#define SCALE 0.125f
#define MTOT (BATCH * NTOK)   // 8256
#define NBH (BATCH * NHEAD)   // 96

// ---------------- scratch (static device globals; allocation-free) ----------
__device__ float d_add[NTOK * NTOK + 64];

__device__ __align__(16) __nv_bfloat16 d_xhi[MTOT * CDIM];
__device__ __align__(16) __nv_bfloat16 d_xlo[MTOT * CDIM];
__device__ __align__(16) __nv_bfloat16 d_wkv_hi[2 * CDIM * CDIM];
__device__ __align__(16) __nv_bfloat16 d_wkv_lo[2 * CDIM * CDIM];
__device__ __align__(16) __nv_bfloat16 d_wp_hi[CDIM * CDIM];
__device__ __align__(16) __nv_bfloat16 d_wp_lo[CDIM * CDIM];
__device__ __align__(16) __nv_bfloat16 d_ohi[MTOT * CDIM];
__device__ __align__(16) __nv_bfloat16 d_olo[MTOT * CDIM];

// K head-major [bh][n][d], V transposed [bh][d][n]; +pad (zero-init) for OOB j reads
__device__ __align__(16) __nv_bfloat16 d_khi[NBH * NTOK * HD + 4096];
__device__ __align__(16) __nv_bfloat16 d_klo[NBH * NTOK * HD + 4096];
__device__ __align__(16) __nv_bfloat16 d_vthi[NBH * HD * NTOK + 4096];
__device__ __align__(16) __nv_bfloat16 d_vtlo[NBH * HD * NTOK + 4096];

// ---------------- helpers ----------------------------------------------------
__device__ __forceinline__ uint32_t swz(uint32_t o) { return o ^ ((o >> 3) & 0x70); }

__device__ __forceinline__ void mma_bf16(float* c, const uint32_t* a,
                                         uint32_t b0, uint32_t b1) {
    asm volatile(
        "mma.sync.aligned.m16n8k16.row.col.f32.bf16.bf16.f32 "
        "{%0,%1,%2,%3}, {%4,%5,%6,%7}, {%8,%9}, {%0,%1,%2,%3};"
        : "+f"(c[0]), "+f"(c[1]), "+f"(c[2]), "+f"(c[3])
        : "r"(a[0]), "r"(a[1]), "r"(a[2]), "r"(a[3]), "r"(b0), "r"(b1));
}
__device__ __forceinline__ uint32_t pack_hi(float a, float b) {
    __nv_bfloat162 p(__float2bfloat16(a), __float2bfloat16(b));
    return *(uint32_t*)&p;
}
__device__ __forceinline__ uint32_t pack_lo(float a, float b, uint32_t hp) {
    __nv_bfloat162 hh = *(__nv_bfloat162*)&hp;
    return pack_hi(a - __bfloat162float(hh.x), b - __bfloat162float(hh.y));
}

// ---------------------------------------------------------------------------
// Kernel 1: gaussian additive bias table
// ---------------------------------------------------------------------------
__global__ void add_kernel() {
    int idx = blockIdx.x * 256 + threadIdx.x;
    if (idx >= NTOK * NTOK + 64) return;
    float v = 0.0f;
    if (idx < NTOK * NTOK) {
        int i = idx / NTOK, j = idx - (idx / NTOK) * NTOK;
        if (i >= 8 && j >= 8) {
            int p = i - 8, q = j - 8;
            int dr = (p >> 5) - (q >> 5);
            int dc = (p & 31) - (q & 31);
            v = __expf(-0.02f * (float)(dr * dr + dc * dc));
        }
    }
    d_add[idx] = v;
}

// ---------------------------------------------------------------------------
// split: fp32 -> bf16 hi + lo (destination by mode, device-side only)
// ---------------------------------------------------------------------------
__global__ void split_kernel(const float* __restrict__ src, int n, int mode) {
    int i = blockIdx.x * 256 + threadIdx.x;
    if (i >= n) return;
    float v = src[i];
    __nv_bfloat16 h = __float2bfloat16(v);
    __nv_bfloat16 l = __float2bfloat16(v - __bfloat162float(h));
    __nv_bfloat16 *dh, *dl;
    if (mode == 0)      { dh = d_xhi;    dl = d_xlo;    }
    else if (mode == 1) { dh = d_wkv_hi; dl = d_wkv_lo; }
    else                { dh = d_wp_hi;  dl = d_wp_lo;  }
    dh[i] = h; dl[i] = l;
}

// ---------------------------------------------------------------------------
// mma.sync GEMM (validated). MODE 0: O.Wp^T -> out. MODE 1: x.Wkv^T -> K/V
// bf16 split stores (K head-major, V transposed).
// ---------------------------------------------------------------------------
#define GM_SMEM_BYTES (4 * 16384)

template <int MODE>
__global__ __launch_bounds__(256)
void gemm_mma(const float* __restrict__ bias, float* __restrict__ out) {
    extern __shared__ char smem[];
    const int tid = threadIdx.x;
    const int wid = tid >> 5;
    const int lane = tid & 31;
    const int g = lane >> 2, t = lane & 3;

    const int m0 = blockIdx.y * 128;
    const int c0 = blockIdx.x * 128;
    const int wm = (wid & 3) * 32;
    const int wn = (wid >> 2) * 64;

    const __nv_bfloat16* Ahi = (MODE == 0) ? d_ohi : d_xhi;
    const __nv_bfloat16* Alo = (MODE == 0) ? d_olo : d_xlo;
    const __nv_bfloat16* Bhi = (MODE == 0) ? d_wp_hi : d_wkv_hi;
    const __nv_bfloat16* Blo = (MODE == 0) ? d_wp_lo : d_wkv_lo;

    float C[2][8][4];
#pragma unroll
    for (int mt = 0; mt < 2; mt++)
#pragma unroll
        for (int nt = 0; nt < 8; nt++)
#pragma unroll
            for (int e = 0; e < 4; e++) C[mt][nt][e] = 0.0f;

    const char* sA_hi = smem;
    const char* sA_lo = smem + 16384;
    const char* sB_hi = smem + 32768;
    const char* sB_lo = smem + 49152;

    for (int kc = 0; kc < CDIM / 64; kc++) {
        const int kt = kc * 64;
        for (int seg = tid; seg < 4096; seg += 256) {
            int buf = seg >> 10;
            int idx = seg & 1023;
            int row = idx >> 3;
            int s = idx & 7;
            const __nv_bfloat16* src;
            size_t grow;
            if (buf < 2) {
                int gg = m0 + row; if (gg > MTOT - 1) gg = MTOT - 1;
                grow = (size_t)gg;
                src = (buf == 0) ? Ahi : Alo;
            } else {
                grow = (size_t)(c0 + row);
                src = (buf == 2) ? Bhi : Blo;
            }
            uint4 v = *(const uint4*)(src + grow * CDIM + kt + s * 8);
            *(uint4*)(smem + buf * 16384 + swz(row * 128 + s * 16)) = v;
        }
        __syncthreads();

#pragma unroll
        for (int ks = 0; ks < 4; ks++) {
            const uint32_t kb = ks * 32 + t * 4;
            uint32_t ah[2][4], al[2][4];
#pragma unroll
            for (int mt = 0; mt < 2; mt++) {
                uint32_t r0 = (uint32_t)(wm + mt * 16 + g) * 128;
                uint32_t r8 = r0 + 8 * 128;
                ah[mt][0] = *(const uint32_t*)(sA_hi + swz(r0 + kb));
                ah[mt][1] = *(const uint32_t*)(sA_hi + swz(r8 + kb));
                ah[mt][2] = *(const uint32_t*)(sA_hi + swz(r0 + kb + 16));
                ah[mt][3] = *(const uint32_t*)(sA_hi + swz(r8 + kb + 16));
                al[mt][0] = *(const uint32_t*)(sA_lo + swz(r0 + kb));
                al[mt][1] = *(const uint32_t*)(sA_lo + swz(r8 + kb));
                al[mt][2] = *(const uint32_t*)(sA_lo + swz(r0 + kb + 16));
                al[mt][3] = *(const uint32_t*)(sA_lo + swz(r8 + kb + 16));
            }
#pragma unroll
            for (int nt = 0; nt < 8; nt++) {
                uint32_t br = (uint32_t)(wn + nt * 8 + g) * 128;
                uint32_t bh0 = *(const uint32_t*)(sB_hi + swz(br + kb));
                uint32_t bh1 = *(const uint32_t*)(sB_hi + swz(br + kb + 16));
                uint32_t bl0 = *(const uint32_t*)(sB_lo + swz(br + kb));
                uint32_t bl1 = *(const uint32_t*)(sB_lo + swz(br + kb + 16));
#pragma unroll
                for (int mt = 0; mt < 2; mt++) {
                    mma_bf16(C[mt][nt], ah[mt], bh0, bh1);
                    mma_bf16(C[mt][nt], ah[mt], bl0, bl1);
                    mma_bf16(C[mt][nt], al[mt], bh0, bh1);
                }
            }
        }
        __syncthreads();
    }

#pragma unroll
    for (int mt = 0; mt < 2; mt++) {
#pragma unroll
        for (int nt = 0; nt < 8; nt++) {
            int col = c0 + wn + nt * 8 + t * 2;
            float bx = bias[col], by = bias[col + 1];
#pragma unroll
            for (int half = 0; half < 2; half++) {
                int row = m0 + wm + mt * 16 + g + half * 8;
                if (row >= MTOT) continue;
                float vx = C[mt][nt][half * 2 + 0] + bx;
                float vy = C[mt][nt][half * 2 + 1] + by;
                if (MODE == 0) {
                    *(float2*)&out[(size_t)row * CDIM + col] = make_float2(vx, vy);
                } else {
                    bool isK = (col < CDIM);
                    int cc = isK ? col : (col - CDIM);
                    int hh = cc >> 6, d = cc & 63;
                    int b = row / NTOK, n = row - (row / NTOK) * NTOK;
                    int bhh = b * NHEAD + hh;
                    __nv_bfloat16 hx = __float2bfloat16(vx);
                    __nv_bfloat16 lx = __float2bfloat16(vx - __bfloat162float(hx));
                    __nv_bfloat16 hy = __float2bfloat16(vy);
                    __nv_bfloat16 ly = __float2bfloat16(vy - __bfloat162float(hy));
                    if (isK) {
                        size_t o = ((size_t)bhh * NTOK + n) * HD + d;
                        *(__nv_bfloat162*)&d_khi[o] = __nv_bfloat162(hx, hy);
                        *(__nv_bfloat162*)&d_klo[o] = __nv_bfloat162(lx, ly);
                    } else {
                        size_t o = ((size_t)bhh * HD + d) * NTOK + n;
                        d_vthi[o] = hx;        d_vtlo[o] = lx;
                        d_vthi[o + NTOK] = hy; d_vtlo[o + NTOK] = ly;
                    }
                }
            }
        }
    }
}

// ---------------------------------------------------------------------------
// Kernel 3: mma flash attention. CTA: 128 i-rows x one bh. 8 warps x 16 rows.
// j-tiles of 64. Ki frags in regs; S-frags repacked in-place as P A-frags.
// ---------------------------------------------------------------------------
__global__ __launch_bounds__(256)
void attn_mma() {
    __shared__ char smem[32768];
    const int tid = threadIdx.x;
    const int wid = tid >> 5;
    const int lane = tid & 31;
    const int g = lane >> 2, t = lane & 3;
    const int i0 = blockIdx.x * 128;
    const int bh = blockIdx.y;
    const int b = bh / NHEAD, hh = bh - b * NHEAD;
    const int wm = wid * 16;

    // ---- phase 1: Ki hi/lo (128x64 bf16 swizzled) -> register A-fragments
    for (int seg = tid; seg < 2048; seg += 256) {
        int buf = seg >> 10;
        int idx = seg & 1023;
        int row = idx >> 3;
        int s = idx & 7;
        int gi = i0 + row; if (gi > NTOK - 1) gi = NTOK - 1;
        const __nv_bfloat16* src = buf ? d_klo : d_khi;
        uint4 v = *(const uint4*)(src + ((size_t)bh * NTOK + gi) * HD + s * 8);
        *(uint4*)(smem + buf * 16384 + swz(row * 128 + s * 16)) = v;
    }
    __syncthreads();

    uint32_t akh[4][4], akl[4][4];
    {
        uint32_t r0 = (uint32_t)(wm + g) * 128;
        uint32_t r8 = r0 + 8 * 128;
#pragma unroll
        for (int ks = 0; ks < 4; ks++) {
            uint32_t kb = ks * 32 + t * 4;
            akh[ks][0] = *(const uint32_t*)(smem + swz(r0 + kb));
            akh[ks][1] = *(const uint32_t*)(smem + swz(r8 + kb));
            akh[ks][2] = *(const uint32_t*)(smem + swz(r0 + kb + 16));
            akh[ks][3] = *(const uint32_t*)(smem + swz(r8 + kb + 16));
            akl[ks][0] = *(const uint32_t*)(smem + 16384 + swz(r0 + kb));
            akl[ks][1] = *(const uint32_t*)(smem + 16384 + swz(r8 + kb));
            akl[ks][2] = *(const uint32_t*)(smem + 16384 + swz(r0 + kb + 16));
            akl[ks][3] = *(const uint32_t*)(smem + 16384 + swz(r8 + kb + 16));
        }
    }
    __syncthreads();

    float m_[2] = {-1e30f, -1e30f};
    float l_[2] = {0.0f, 0.0f};
    float Oc[8][4];
#pragma unroll
    for (int nt = 0; nt < 8; nt++)
#pragma unroll
        for (int e = 0; e < 4; e++) Oc[nt][e] = 0.0f;

    const int r0g = i0 + wm + g;
    const int r1g = r0g + 8;
    const int ar0 = (r0g < NTOK) ? r0g : (NTOK - 1);
    const int ar1 = (r1g < NTOK) ? r1g : (NTOK - 1);

    const int NJT = (NTOK + 63) / 64;   // 17
    for (int jt = 0; jt < NJT; jt++) {
        const int j0 = jt * 64;
        // smem: [0,8K) Kj hi | [8K,16K) Kj lo | [16K,24K) VT hi | [24K,32K) VT lo
        for (int seg = tid; seg < 2048; seg += 256) {
            int buf = seg >> 9;
            int idx = seg & 511;
            int row = idx >> 3;
            int s = idx & 7;
            const __nv_bfloat16* src;
            size_t off;
            if (buf < 2) {
                src = buf ? d_klo : d_khi;
                off = ((size_t)bh * NTOK + (j0 + row)) * HD + s * 8;   // pad-safe
            } else {
                src = (buf == 3) ? d_vtlo : d_vthi;
                off = ((size_t)bh * HD + row) * NTOK + j0 + s * 8;     // pad-safe
            }
            uint4 v = *(const uint4*)(src + off);
            *(uint4*)(smem + buf * 8192 + swz(row * 128 + s * 16)) = v;
        }
        __syncthreads();

        // ---- S = Ki . Kj^T (3-product split) ----
        float S[8][4];
#pragma unroll
        for (int nt = 0; nt < 8; nt++)
#pragma unroll
            for (int e = 0; e < 4; e++) S[nt][e] = 0.0f;
#pragma unroll
        for (int ks = 0; ks < 4; ks++) {
            const uint32_t kb = ks * 32 + t * 4;
#pragma unroll
            for (int nt = 0; nt < 8; nt++) {
                uint32_t br = (uint32_t)(nt * 8 + g) * 128;
                uint32_t b0h = *(const uint32_t*)(smem + swz(br + kb));
                uint32_t b1h = *(const uint32_t*)(smem + swz(br + kb + 16));
                uint32_t b0l = *(const uint32_t*)(smem + 8192 + swz(br + kb));
                uint32_t b1l = *(const uint32_t*)(smem + 8192 + swz(br + kb + 16));
                mma_bf16(S[nt], akh[ks], b0h, b1h);
                mma_bf16(S[nt], akh[ks], b0l, b1l);
                mma_bf16(S[nt], akl[ks], b0h, b1h);
            }
        }

        // ---- scale + add + mask; online softmax (quad-local) ----
        float mt0 = -1e30f, mt1 = -1e30f;
#pragma unroll
        for (int nt = 0; nt < 8; nt++) {
            int col = j0 + nt * 8 + t * 2;
            bool ok = (col < NTOK);   // col even, NTOK even -> covers col+1
            float2 a0 = *(const float2*)(d_add + (size_t)ar0 * NTOK + col);
            float2 a1 = *(const float2*)(d_add + (size_t)ar1 * NTOK + col);
            S[nt][0] = ok ? S[nt][0] * SCALE + a0.x : -1e30f;
            S[nt][1] = ok ? S[nt][1] * SCALE + a0.y : -1e30f;
            S[nt][2] = ok ? S[nt][2] * SCALE + a1.x : -1e30f;
            S[nt][3] = ok ? S[nt][3] * SCALE + a1.y : -1e30f;
            mt0 = fmaxf(mt0, fmaxf(S[nt][0], S[nt][1]));
            mt1 = fmaxf(mt1, fmaxf(S[nt][2], S[nt][3]));
        }
        mt0 = fmaxf(mt0, __shfl_xor_sync(0xffffffffu, mt0, 1));
        mt0 = fmaxf(mt0, __shfl_xor_sync(0xffffffffu, mt0, 2));
        mt1 = fmaxf(mt1, __shfl_xor_sync(0xffffffffu, mt1, 1));
        mt1 = fmaxf(mt1, __shfl_xor_sync(0xffffffffu, mt1, 2));
        float mn0 = fmaxf(m_[0], mt0), mn1 = fmaxf(m_[1], mt1);
        float cr0 = __expf(m_[0] - mn0), cr1 = __expf(m_[1] - mn1);
        float rs0 = 0.0f, rs1 = 0.0f;
#pragma unroll
        for (int nt = 0; nt < 8; nt++) {
            S[nt][0] = __expf(S[nt][0] - mn0);
            S[nt][1] = __expf(S[nt][1] - mn0);
            S[nt][2] = __expf(S[nt][2] - mn1);
            S[nt][3] = __expf(S[nt][3] - mn1);
            rs0 += S[nt][0] + S[nt][1];
            rs1 += S[nt][2] + S[nt][3];
        }
        rs0 += __shfl_xor_sync(0xffffffffu, rs0, 1);
        rs0 += __shfl_xor_sync(0xffffffffu, rs0, 2);
        rs1 += __shfl_xor_sync(0xffffffffu, rs1, 1);
        rs1 += __shfl_xor_sync(0xffffffffu, rs1, 2);
        l_[0] = l_[0] * cr0 + rs0;
        l_[1] = l_[1] * cr1 + rs1;
        m_[0] = mn0; m_[1] = mn1;
#pragma unroll
        for (int nt = 0; nt < 8; nt++) {
            Oc[nt][0] *= cr0; Oc[nt][1] *= cr0;
            Oc[nt][2] *= cr1; Oc[nt][3] *= cr1;
        }

        // ---- pack P into A-fragments (hi/lo), O += P . V ----
#pragma unroll
        for (int ks = 0; ks < 4; ks++) {
            uint32_t ph[4], pl[4];
            ph[0] = pack_hi(S[2 * ks][0], S[2 * ks][1]);
            ph[1] = pack_hi(S[2 * ks][2], S[2 * ks][3]);
            ph[2] = pack_hi(S[2 * ks + 1][0], S[2 * ks + 1][1]);
            ph[3] = pack_hi(S[2 * ks + 1][2], S[2 * ks + 1][3]);
            pl[0] = pack_lo(S[2 * ks][0], S[2 * ks][1], ph[0]);
            pl[1] = pack_lo(S[2 * ks][2], S[2 * ks][3], ph[1]);
            pl[2] = pack_lo(S[2 * ks + 1][0], S[2 * ks + 1][1], ph[2]);
            pl[3] = pack_lo(S[2 * ks + 1][2], S[2 * ks + 1][3], ph[3]);
            const uint32_t kb = ks * 32 + t * 4;
#pragma unroll
            for (int nd = 0; nd < 8; nd++) {
                uint32_t br = (uint32_t)(nd * 8 + g) * 128;
                uint32_t b0h = *(const uint32_t*)(smem + 16384 + swz(br + kb));
                uint32_t b1h = *(const uint32_t*)(smem + 16384 + swz(br + kb + 16));
                uint32_t b0l = *(const uint32_t*)(smem + 24576 + swz(br + kb));
                uint32_t b1l = *(const uint32_t*)(smem + 24576 + swz(br + kb + 16));
                mma_bf16(Oc[nd], ph, b0h, b1h);
                mma_bf16(Oc[nd], ph, b0l, b1l);
                mma_bf16(Oc[nd], pl, b0h, b1h);
            }
        }
        __syncthreads();
    }

    // ---- finalize: O / l, bf16 hi/lo split -> d_ohi/d_olo ----
    float inv0 = 1.0f / l_[0], inv1 = 1.0f / l_[1];
#pragma unroll
    for (int nd = 0; nd < 8; nd++) {
        int d = nd * 8 + t * 2;
        if (r0g < NTOK) {
            float vx = Oc[nd][0] * inv0, vy = Oc[nd][1] * inv0;
            uint32_t hp = pack_hi(vx, vy);
            uint32_t lp = pack_lo(vx, vy, hp);
            size_t o = ((size_t)b * NTOK + r0g) * CDIM + hh * HD + d;
            *(uint32_t*)&d_ohi[o] = hp;
            *(uint32_t*)&d_olo[o] = lp;
        }
        if (r1g < NTOK) {
            float vx = Oc[nd][2] * inv1, vy = Oc[nd][3] * inv1;
            uint32_t hp = pack_hi(vx, vy);
            uint32_t lp = pack_lo(vx, vy, hp);
            size_t o = ((size_t)b * NTOK + r1g) * CDIM + hh * HD + d;
            *(uint32_t*)&d_ohi[o] = hp;
            *(uint32_t*)&d_olo[o] = lp;
        }
    }
}

// ---------------------------------------------------------------------------
extern "C" void kernel_launch(void* const* d_in, const int* in_sizes, int n_in,
                              void* d_out, int out_size) {
    const float* x = 0;
    const float* qkv_w = 0;
    const float* qkv_b = 0;
    const float* proj_w = 0;
    const float* proj_b = 0;
    for (int i = 0; i < n_in; i++) {
        switch (in_sizes[i]) {
            case 6340608: x      = (const float*)d_in[i]; break;
            case 1769472: qkv_w  = (const float*)d_in[i]; break;
            case 2304:    qkv_b  = (const float*)d_in[i]; break;
            case 589824:  proj_w = (const float*)d_in[i]; break;
            case 768:     proj_b = (const float*)d_in[i]; break;
            default: break;
        }
    }
    float* out = (float*)d_out;

    cudaFuncSetAttribute(gemm_mma<0>,
                         cudaFuncAttributeMaxDynamicSharedMemorySize, GM_SMEM_BYTES);
    cudaFuncSetAttribute(gemm_mma<1>,
                         cudaFuncAttributeMaxDynamicSharedMemorySize, GM_SMEM_BYTES);

    add_kernel<<<(NTOK * NTOK + 64 + 255) / 256, 256>>>();

    const int NX = MTOT * CDIM;
    const int NWKV = 2 * CDIM * CDIM;
    const int NWP = CDIM * CDIM;
    split_kernel<<<(NX + 255) / 256, 256>>>(x, NX, 0);
    split_kernel<<<(NWKV + 255) / 256, 256>>>(qkv_w + (size_t)CDIM * CDIM, NWKV, 1);
    split_kernel<<<(NWP + 255) / 256, 256>>>(proj_w, NWP, 2);

    gemm_mma<1><<<dim3(12, 65), 256, GM_SMEM_BYTES>>>(qkv_b + CDIM, nullptr);

    attn_mma<<<dim3((NTOK + 127) / 128, NBH), 256>>>();

    gemm_mma<0><<<dim3(6, 65), 256, GM_SMEM_BYTES>>>(proj_b, out);
}

// round 12
// speedup vs baseline: 2.8230x; 1.3220x over previous
#include <cuda_runtime.h>
#include <cuda_bf16.h>
#include <cstdint>

#define BATCH 8
#define NTOK 1032
#define CDIM 768
#define NHEAD 12
#define HD 64
#define SCALE 0.125f
#define MTOT (BATCH * NTOK)   // 8256
#define NBH (BATCH * NHEAD)   // 96

// ---------------- scratch (static device globals; allocation-free) ----------
__device__ float d_add[NTOK * NTOK + 64];

__device__ __align__(16) __nv_bfloat16 d_xhi[MTOT * CDIM];
__device__ __align__(16) __nv_bfloat16 d_xlo[MTOT * CDIM];
__device__ __align__(16) __nv_bfloat16 d_wkv_hi[2 * CDIM * CDIM];
__device__ __align__(16) __nv_bfloat16 d_wkv_lo[2 * CDIM * CDIM];
__device__ __align__(16) __nv_bfloat16 d_wp_hi[CDIM * CDIM];
__device__ __align__(16) __nv_bfloat16 d_wp_lo[CDIM * CDIM];
__device__ __align__(16) __nv_bfloat16 d_ohi[MTOT * CDIM];
__device__ __align__(16) __nv_bfloat16 d_olo[MTOT * CDIM];

// K head-major [bh][n][d], V transposed [bh][d][n]; +pad (zero-init) for OOB j reads
__device__ __align__(16) __nv_bfloat16 d_khi[NBH * NTOK * HD + 4096];
__device__ __align__(16) __nv_bfloat16 d_klo[NBH * NTOK * HD + 4096];
__device__ __align__(16) __nv_bfloat16 d_vthi[NBH * HD * NTOK + 4096];
__device__ __align__(16) __nv_bfloat16 d_vtlo[NBH * HD * NTOK + 4096];

// ---------------- helpers ----------------------------------------------------
__device__ __forceinline__ uint32_t swz(uint32_t o) { return o ^ ((o >> 3) & 0x70); }

__device__ __forceinline__ uint32_t smem_u32(const void* p) {
    uint32_t a;
    asm("{ .reg .u64 t; cvta.to.shared.u64 t, %1; cvt.u32.u64 %0, t; }"
        : "=r"(a) : "l"(p));
    return a;
}
__device__ __forceinline__ void cp16(uint32_t dst, const void* src) {
    asm volatile("cp.async.cg.shared.global [%0], [%1], 16;"
                 :: "r"(dst), "l"(src) : "memory");
}
#define CP_COMMIT() asm volatile("cp.async.commit_group;" ::: "memory")
#define CP_WAIT0()  asm volatile("cp.async.wait_group 0;" ::: "memory")
#define CP_WAIT1()  asm volatile("cp.async.wait_group 1;" ::: "memory")

__device__ __forceinline__ void mma_bf16(float* c, const uint32_t* a,
                                         uint32_t b0, uint32_t b1) {
    asm volatile(
        "mma.sync.aligned.m16n8k16.row.col.f32.bf16.bf16.f32 "
        "{%0,%1,%2,%3}, {%4,%5,%6,%7}, {%8,%9}, {%0,%1,%2,%3};"
        : "+f"(c[0]), "+f"(c[1]), "+f"(c[2]), "+f"(c[3])
        : "r"(a[0]), "r"(a[1]), "r"(a[2]), "r"(a[3]), "r"(b0), "r"(b1));
}
__device__ __forceinline__ uint32_t pack_hi(float a, float b) {
    __nv_bfloat162 p(__float2bfloat16(a), __float2bfloat16(b));
    return *(uint32_t*)&p;
}
__device__ __forceinline__ uint32_t pack_lo(float a, float b, uint32_t hp) {
    __nv_bfloat162 hh = *(__nv_bfloat162*)&hp;
    return pack_hi(a - __bfloat162float(hh.x), b - __bfloat162float(hh.y));
}

// ---------------------------------------------------------------------------
// Kernel 1: gaussian additive bias table
// ---------------------------------------------------------------------------
__global__ void add_kernel() {
    int idx = blockIdx.x * 256 + threadIdx.x;
    if (idx >= NTOK * NTOK + 64) return;
    float v = 0.0f;
    if (idx < NTOK * NTOK) {
        int i = idx / NTOK, j = idx - (idx / NTOK) * NTOK;
        if (i >= 8 && j >= 8) {
            int p = i - 8, q = j - 8;
            int dr = (p >> 5) - (q >> 5);
            int dc = (p & 31) - (q & 31);
            v = __expf(-0.02f * (float)(dr * dr + dc * dc));
        }
    }
    d_add[idx] = v;
}

// ---------------------------------------------------------------------------
// split: fp32 -> bf16 hi + lo (destination by mode, device-side only)
// ---------------------------------------------------------------------------
__global__ void split_kernel(const float* __restrict__ src, int n, int mode) {
    int i = blockIdx.x * 256 + threadIdx.x;
    if (i >= n) return;
    float v = src[i];
    __nv_bfloat16 h = __float2bfloat16(v);
    __nv_bfloat16 l = __float2bfloat16(v - __bfloat162float(h));
    __nv_bfloat16 *dh, *dl;
    if (mode == 0)      { dh = d_xhi;    dl = d_xlo;    }
    else if (mode == 1) { dh = d_wkv_hi; dl = d_wkv_lo; }
    else                { dh = d_wp_hi;  dl = d_wp_lo;  }
    dh[i] = h; dl[i] = l;
}

// ---------------------------------------------------------------------------
// mma GEMM with cp.async double buffering.
// MODE 0: O.Wp^T -> out. MODE 1: x.Wkv^T -> K/V (bf16 split, V transposed).
// CTA 128x128, 8 warps, K-chunk 64, SW128. smem: 2 x (4 x 16KB) = 128KB.
// ---------------------------------------------------------------------------
#define GM_STAGE_BYTES 65536
#define GM_SMEM_BYTES (2 * GM_STAGE_BYTES)
#define NKC (CDIM / 64)   // 12

template <int MODE>
__global__ __launch_bounds__(256)
void gemm_mma(const float* __restrict__ bias, float* __restrict__ out) {
    extern __shared__ char smem[];
    const uint32_t sb = smem_u32(smem);
    const int tid = threadIdx.x;
    const int wid = tid >> 5;
    const int lane = tid & 31;
    const int g = lane >> 2, t = lane & 3;

    const int m0 = blockIdx.y * 128;
    const int c0 = blockIdx.x * 128;
    const int wm = (wid & 3) * 32;
    const int wn = (wid >> 2) * 64;

    const __nv_bfloat16* Ahi = (MODE == 0) ? d_ohi : d_xhi;
    const __nv_bfloat16* Alo = (MODE == 0) ? d_olo : d_xlo;
    const __nv_bfloat16* Bhi = (MODE == 0) ? d_wp_hi : d_wkv_hi;
    const __nv_bfloat16* Blo = (MODE == 0) ? d_wp_lo : d_wkv_lo;

    float C[2][8][4];
#pragma unroll
    for (int mt = 0; mt < 2; mt++)
#pragma unroll
        for (int nt = 0; nt < 8; nt++)
#pragma unroll
            for (int e = 0; e < 4; e++) C[mt][nt][e] = 0.0f;

    // issue one k-chunk's loads into stage
    auto issue = [&](int kc, uint32_t stage) {
        const int kt = kc * 64;
#pragma unroll
        for (int ss = 0; ss < 16; ss++) {
            int seg = tid + ss * 256;
            int buf = seg >> 10;
            int idx = seg & 1023;
            int row = idx >> 3;
            int s = idx & 7;
            const __nv_bfloat16* src;
            size_t grow;
            if (buf < 2) {
                int gg = m0 + row; if (gg > MTOT - 1) gg = MTOT - 1;
                grow = (size_t)gg;
                src = (buf == 0) ? Ahi : Alo;
            } else {
                grow = (size_t)(c0 + row);
                src = (buf == 2) ? Bhi : Blo;
            }
            cp16(stage + buf * 16384 + swz(row * 128 + s * 16),
                 src + grow * CDIM + kt + s * 8);
        }
        CP_COMMIT();
    };

    issue(0, sb);
    for (int kc = 0; kc < NKC; kc++) {
        if (kc + 1 < NKC) { issue(kc + 1, sb + ((kc + 1) & 1) * GM_STAGE_BYTES); CP_WAIT1(); }
        else              { CP_WAIT0(); }
        __syncthreads();

        const char* st = smem + (kc & 1) * GM_STAGE_BYTES;
        const char* sA_hi = st;
        const char* sA_lo = st + 16384;
        const char* sB_hi = st + 32768;
        const char* sB_lo = st + 49152;

#pragma unroll
        for (int ks = 0; ks < 4; ks++) {
            const uint32_t kb = ks * 32 + t * 4;
            uint32_t ah[2][4], al[2][4];
#pragma unroll
            for (int mt = 0; mt < 2; mt++) {
                uint32_t r0 = (uint32_t)(wm + mt * 16 + g) * 128;
                uint32_t r8 = r0 + 8 * 128;
                ah[mt][0] = *(const uint32_t*)(sA_hi + swz(r0 + kb));
                ah[mt][1] = *(const uint32_t*)(sA_hi + swz(r8 + kb));
                ah[mt][2] = *(const uint32_t*)(sA_hi + swz(r0 + kb + 16));
                ah[mt][3] = *(const uint32_t*)(sA_hi + swz(r8 + kb + 16));
                al[mt][0] = *(const uint32_t*)(sA_lo + swz(r0 + kb));
                al[mt][1] = *(const uint32_t*)(sA_lo + swz(r8 + kb));
                al[mt][2] = *(const uint32_t*)(sA_lo + swz(r0 + kb + 16));
                al[mt][3] = *(const uint32_t*)(sA_lo + swz(r8 + kb + 16));
            }
#pragma unroll
            for (int nt = 0; nt < 8; nt++) {
                uint32_t br = (uint32_t)(wn + nt * 8 + g) * 128;
                uint32_t bh0 = *(const uint32_t*)(sB_hi + swz(br + kb));
                uint32_t bh1 = *(const uint32_t*)(sB_hi + swz(br + kb + 16));
                uint32_t bl0 = *(const uint32_t*)(sB_lo + swz(br + kb));
                uint32_t bl1 = *(const uint32_t*)(sB_lo + swz(br + kb + 16));
#pragma unroll
                for (int mt = 0; mt < 2; mt++) {
                    mma_bf16(C[mt][nt], ah[mt], bh0, bh1);
                    mma_bf16(C[mt][nt], ah[mt], bl0, bl1);
                    mma_bf16(C[mt][nt], al[mt], bh0, bh1);
                }
            }
        }
        __syncthreads();
    }

#pragma unroll
    for (int mt = 0; mt < 2; mt++) {
#pragma unroll
        for (int nt = 0; nt < 8; nt++) {
            int col = c0 + wn + nt * 8 + t * 2;
            float bx = bias[col], by = bias[col + 1];
#pragma unroll
            for (int half = 0; half < 2; half++) {
                int row = m0 + wm + mt * 16 + g + half * 8;
                if (row >= MTOT) continue;
                float vx = C[mt][nt][half * 2 + 0] + bx;
                float vy = C[mt][nt][half * 2 + 1] + by;
                if (MODE == 0) {
                    *(float2*)&out[(size_t)row * CDIM + col] = make_float2(vx, vy);
                } else {
                    bool isK = (col < CDIM);
                    int cc = isK ? col : (col - CDIM);
                    int hh = cc >> 6, d = cc & 63;
                    int b = row / NTOK, n = row - (row / NTOK) * NTOK;
                    int bhh = b * NHEAD + hh;
                    __nv_bfloat16 hx = __float2bfloat16(vx);
                    __nv_bfloat16 lx = __float2bfloat16(vx - __bfloat162float(hx));
                    __nv_bfloat16 hy = __float2bfloat16(vy);
                    __nv_bfloat16 ly = __float2bfloat16(vy - __bfloat162float(hy));
                    if (isK) {
                        size_t o = ((size_t)bhh * NTOK + n) * HD + d;
                        *(__nv_bfloat162*)&d_khi[o] = __nv_bfloat162(hx, hy);
                        *(__nv_bfloat162*)&d_klo[o] = __nv_bfloat162(lx, ly);
                    } else {
                        size_t o = ((size_t)bhh * HD + d) * NTOK + n;
                        d_vthi[o] = hx;        d_vtlo[o] = lx;
                        d_vthi[o + NTOK] = hy; d_vtlo[o + NTOK] = ly;
                    }
                }
            }
        }
    }
}

// ---------------------------------------------------------------------------
// Kernel 3: mma flash attention with cp.async double-buffered j-tiles.
// CTA: 128 i-rows x one bh. 8 warps x 16 rows. smem: 2 x 32KB stages.
// ---------------------------------------------------------------------------
#define AT_STAGE_BYTES 32768
#define AT_SMEM_BYTES (2 * AT_STAGE_BYTES)

__global__ __launch_bounds__(256)
void attn_mma() {
    extern __shared__ char smem[];
    const uint32_t sb = smem_u32(smem);
    const int tid = threadIdx.x;
    const int wid = tid >> 5;
    const int lane = tid & 31;
    const int g = lane >> 2, t = lane & 3;
    const int i0 = blockIdx.x * 128;
    const int bh = blockIdx.y;
    const int b = bh / NHEAD, hh = bh - b * NHEAD;
    const int wm = wid * 16;

    // ---- phase 1: Ki hi/lo -> register A-fragments (staged in buffer 0)
    for (int seg = tid; seg < 2048; seg += 256) {
        int buf = seg >> 10;
        int idx = seg & 1023;
        int row = idx >> 3;
        int s = idx & 7;
        int gi = i0 + row; if (gi > NTOK - 1) gi = NTOK - 1;
        const __nv_bfloat16* src = buf ? d_klo : d_khi;
        uint4 v = *(const uint4*)(src + ((size_t)bh * NTOK + gi) * HD + s * 8);
        *(uint4*)(smem + buf * 16384 + swz(row * 128 + s * 16)) = v;
    }
    __syncthreads();

    uint32_t akh[4][4], akl[4][4];
    {
        uint32_t r0 = (uint32_t)(wm + g) * 128;
        uint32_t r8 = r0 + 8 * 128;
#pragma unroll
        for (int ks = 0; ks < 4; ks++) {
            uint32_t kb = ks * 32 + t * 4;
            akh[ks][0] = *(const uint32_t*)(smem + swz(r0 + kb));
            akh[ks][1] = *(const uint32_t*)(smem + swz(r8 + kb));
            akh[ks][2] = *(const uint32_t*)(smem + swz(r0 + kb + 16));
            akh[ks][3] = *(const uint32_t*)(smem + swz(r8 + kb + 16));
            akl[ks][0] = *(const uint32_t*)(smem + 16384 + swz(r0 + kb));
            akl[ks][1] = *(const uint32_t*)(smem + 16384 + swz(r8 + kb));
            akl[ks][2] = *(const uint32_t*)(smem + 16384 + swz(r0 + kb + 16));
            akl[ks][3] = *(const uint32_t*)(smem + 16384 + swz(r8 + kb + 16));
        }
    }
    __syncthreads();

    float m_[2] = {-1e30f, -1e30f};
    float l_[2] = {0.0f, 0.0f};
    float Oc[8][4];
#pragma unroll
    for (int nt = 0; nt < 8; nt++)
#pragma unroll
        for (int e = 0; e < 4; e++) Oc[nt][e] = 0.0f;

    const int r0g = i0 + wm + g;
    const int r1g = r0g + 8;
    const int ar0 = (r0g < NTOK) ? r0g : (NTOK - 1);
    const int ar1 = (r1g < NTOK) ? r1g : (NTOK - 1);

    // j-tile loader: smem stage = [0,8K) Kj hi | [8K) Kj lo | [16K) VT hi | [24K) VT lo
    auto issue_j = [&](int jt, uint32_t stage) {
        const int j0 = jt * 64;
#pragma unroll
        for (int ss = 0; ss < 8; ss++) {
            int seg = tid + ss * 256;
            int buf = seg >> 9;
            int idx = seg & 511;
            int row = idx >> 3;
            int s = idx & 7;
            const __nv_bfloat16* src;
            size_t off;
            if (buf < 2) {
                src = buf ? d_klo : d_khi;
                off = ((size_t)bh * NTOK + (j0 + row)) * HD + s * 8;   // pad-safe
            } else {
                src = (buf == 3) ? d_vtlo : d_vthi;
                off = ((size_t)bh * HD + row) * NTOK + j0 + s * 8;     // pad-safe
            }
            cp16(stage + buf * 8192 + swz(row * 128 + s * 16), src + off);
        }
        CP_COMMIT();
    };

    const int NJT = (NTOK + 63) / 64;   // 17
    issue_j(0, sb);
    for (int jt = 0; jt < NJT; jt++) {
        if (jt + 1 < NJT) { issue_j(jt + 1, sb + ((jt + 1) & 1) * AT_STAGE_BYTES); CP_WAIT1(); }
        else              { CP_WAIT0(); }
        __syncthreads();

        const char* st = smem + (jt & 1) * AT_STAGE_BYTES;
        const int j0 = jt * 64;

        // ---- S = Ki . Kj^T (3-product split) ----
        float S[8][4];
#pragma unroll
        for (int nt = 0; nt < 8; nt++)
#pragma unroll
            for (int e = 0; e < 4; e++) S[nt][e] = 0.0f;
#pragma unroll
        for (int ks = 0; ks < 4; ks++) {
            const uint32_t kb = ks * 32 + t * 4;
#pragma unroll
            for (int nt = 0; nt < 8; nt++) {
                uint32_t br = (uint32_t)(nt * 8 + g) * 128;
                uint32_t b0h = *(const uint32_t*)(st + swz(br + kb));
                uint32_t b1h = *(const uint32_t*)(st + swz(br + kb + 16));
                uint32_t b0l = *(const uint32_t*)(st + 8192 + swz(br + kb));
                uint32_t b1l = *(const uint32_t*)(st + 8192 + swz(br + kb + 16));
                mma_bf16(S[nt], akh[ks], b0h, b1h);
                mma_bf16(S[nt], akh[ks], b0l, b1l);
                mma_bf16(S[nt], akl[ks], b0h, b1h);
            }
        }

        // ---- scale + add + mask; online softmax (quad-local) ----
        float mt0 = -1e30f, mt1 = -1e30f;
#pragma unroll
        for (int nt = 0; nt < 8; nt++) {
            int col = j0 + nt * 8 + t * 2;
            bool ok = (col < NTOK);
            float2 a0 = *(const float2*)(d_add + (size_t)ar0 * NTOK + col);
            float2 a1 = *(const float2*)(d_add + (size_t)ar1 * NTOK + col);
            S[nt][0] = ok ? S[nt][0] * SCALE + a0.x : -1e30f;
            S[nt][1] = ok ? S[nt][1] * SCALE + a0.y : -1e30f;
            S[nt][2] = ok ? S[nt][2] * SCALE + a1.x : -1e30f;
            S[nt][3] = ok ? S[nt][3] * SCALE + a1.y : -1e30f;
            mt0 = fmaxf(mt0, fmaxf(S[nt][0], S[nt][1]));
            mt1 = fmaxf(mt1, fmaxf(S[nt][2], S[nt][3]));
        }
        mt0 = fmaxf(mt0, __shfl_xor_sync(0xffffffffu, mt0, 1));
        mt0 = fmaxf(mt0, __shfl_xor_sync(0xffffffffu, mt0, 2));
        mt1 = fmaxf(mt1, __shfl_xor_sync(0xffffffffu, mt1, 1));
        mt1 = fmaxf(mt1, __shfl_xor_sync(0xffffffffu, mt1, 2));
        float mn0 = fmaxf(m_[0], mt0), mn1 = fmaxf(m_[1], mt1);
        float cr0 = __expf(m_[0] - mn0), cr1 = __expf(m_[1] - mn1);
        float rs0 = 0.0f, rs1 = 0.0f;
#pragma unroll
        for (int nt = 0; nt < 8; nt++) {
            S[nt][0] = __expf(S[nt][0] - mn0);
            S[nt][1] = __expf(S[nt][1] - mn0);
            S[nt][2] = __expf(S[nt][2] - mn1);
            S[nt][3] = __expf(S[nt][3] - mn1);
            rs0 += S[nt][0] + S[nt][1];
            rs1 += S[nt][2] + S[nt][3];
        }
        rs0 += __shfl_xor_sync(0xffffffffu, rs0, 1);
        rs0 += __shfl_xor_sync(0xffffffffu, rs0, 2);
        rs1 += __shfl_xor_sync(0xffffffffu, rs1, 1);
        rs1 += __shfl_xor_sync(0xffffffffu, rs1, 2);
        l_[0] = l_[0] * cr0 + rs0;
        l_[1] = l_[1] * cr1 + rs1;
        m_[0] = mn0; m_[1] = mn1;
#pragma unroll
        for (int nt = 0; nt < 8; nt++) {
            Oc[nt][0] *= cr0; Oc[nt][1] *= cr0;
            Oc[nt][2] *= cr1; Oc[nt][3] *= cr1;
        }

        // ---- pack P into A-fragments (hi/lo), O += P . V ----
#pragma unroll
        for (int ks = 0; ks < 4; ks++) {
            uint32_t ph[4], pl[4];
            ph[0] = pack_hi(S[2 * ks][0], S[2 * ks][1]);
            ph[1] = pack_hi(S[2 * ks][2], S[2 * ks][3]);
            ph[2] = pack_hi(S[2 * ks + 1][0], S[2 * ks + 1][1]);
            ph[3] = pack_hi(S[2 * ks + 1][2], S[2 * ks + 1][3]);
            pl[0] = pack_lo(S[2 * ks][0], S[2 * ks][1], ph[0]);
            pl[1] = pack_lo(S[2 * ks][2], S[2 * ks][3], ph[1]);
            pl[2] = pack_lo(S[2 * ks + 1][0], S[2 * ks + 1][1], ph[2]);
            pl[3] = pack_lo(S[2 * ks + 1][2], S[2 * ks + 1][3], ph[3]);
            const uint32_t kb = ks * 32 + t * 4;
#pragma unroll
            for (int nd = 0; nd < 8; nd++) {
                uint32_t br = (uint32_t)(nd * 8 + g) * 128;
                uint32_t b0h = *(const uint32_t*)(st + 16384 + swz(br + kb));
                uint32_t b1h = *(const uint32_t*)(st + 16384 + swz(br + kb + 16));
                uint32_t b0l = *(const uint32_t*)(st + 24576 + swz(br + kb));
                uint32_t b1l = *(const uint32_t*)(st + 24576 + swz(br + kb + 16));
                mma_bf16(Oc[nd], ph, b0h, b1h);
                mma_bf16(Oc[nd], ph, b0l, b1l);
                mma_bf16(Oc[nd], pl, b0h, b1h);
            }
        }
        __syncthreads();
    }

    // ---- finalize ----
    float inv0 = 1.0f / l_[0], inv1 = 1.0f / l_[1];
#pragma unroll
    for (int nd = 0; nd < 8; nd++) {
        int d = nd * 8 + t * 2;
        if (r0g < NTOK) {
            float vx = Oc[nd][0] * inv0, vy = Oc[nd][1] * inv0;
            uint32_t hp = pack_hi(vx, vy);
            uint32_t lp = pack_lo(vx, vy, hp);
            size_t o = ((size_t)b * NTOK + r0g) * CDIM + hh * HD + d;
            *(uint32_t*)&d_ohi[o] = hp;
            *(uint32_t*)&d_olo[o] = lp;
        }
        if (r1g < NTOK) {
            float vx = Oc[nd][2] * inv1, vy = Oc[nd][3] * inv1;
            uint32_t hp = pack_hi(vx, vy);
            uint32_t lp = pack_lo(vx, vy, hp);
            size_t o = ((size_t)b * NTOK + r1g) * CDIM + hh * HD + d;
            *(uint32_t*)&d_ohi[o] = hp;
            *(uint32_t*)&d_olo[o] = lp;
        }
    }
}

// ---------------------------------------------------------------------------
extern "C" void kernel_launch(void* const* d_in, const int* in_sizes, int n_in,
                              void* d_out, int out_size) {
    const float* x = 0;
    const float* qkv_w = 0;
    const float* qkv_b = 0;
    const float* proj_w = 0;
    const float* proj_b = 0;
    for (int i = 0; i < n_in; i++) {
        switch (in_sizes[i]) {
            case 6340608: x      = (const float*)d_in[i]; break;
            case 1769472: qkv_w  = (const float*)d_in[i]; break;
            case 2304:    qkv_b  = (const float*)d_in[i]; break;
            case 589824:  proj_w = (const float*)d_in[i]; break;
            case 768:     proj_b = (const float*)d_in[i]; break;
            default: break;
        }
    }
    float* out = (float*)d_out;

    cudaFuncSetAttribute(gemm_mma<0>,
                         cudaFuncAttributeMaxDynamicSharedMemorySize, GM_SMEM_BYTES);
    cudaFuncSetAttribute(gemm_mma<1>,
                         cudaFuncAttributeMaxDynamicSharedMemorySize, GM_SMEM_BYTES);
    cudaFuncSetAttribute(attn_mma,
                         cudaFuncAttributeMaxDynamicSharedMemorySize, AT_SMEM_BYTES);

    add_kernel<<<(NTOK * NTOK + 64 + 255) / 256, 256>>>();

    const int NX = MTOT * CDIM;
    const int NWKV = 2 * CDIM * CDIM;
    const int NWP = CDIM * CDIM;
    split_kernel<<<(NX + 255) / 256, 256>>>(x, NX, 0);
    split_kernel<<<(NWKV + 255) / 256, 256>>>(qkv_w + (size_t)CDIM * CDIM, NWKV, 1);
    split_kernel<<<(NWP + 255) / 256, 256>>>(proj_w, NWP, 2);

    gemm_mma<1><<<dim3(12, 65), 256, GM_SMEM_BYTES>>>(qkv_b + CDIM, nullptr);

    attn_mma<<<dim3((NTOK + 127) / 128, NBH), 256, AT_SMEM_BYTES>>>();

    gemm_mma<0><<<dim3(6, 65), 256, GM_SMEM_BYTES>>>(proj_b, out);
}